// round 1
// baseline (speedup 1.0000x reference)
#include <cuda_runtime.h>
#include <cstdint>
#include <cstddef>

#define Bsz 4
#define Tseq 2048
#define Dm 512
#define Hh 8
#define FFd 2048
#define NLAYER 4
#define ROWS (Bsz*Tseq)   /* 8192 */

// ---------------- scratch (device globals; no allocations allowed) ----------
__device__ float g_x  [ROWS*Dm];      // 16 MB
__device__ float g_y  [ROWS*Dm];      // 16 MB
__device__ float g_att[ROWS*Dm];      // 16 MB
__device__ float g_qkv[ROWS*3*Dm];    // 48 MB
__device__ float g_ff [ROWS*FFd];     // 64 MB

// ---------------- packed f32x2 helpers (Blackwell FFMA2) --------------------
__device__ __forceinline__ void ffma2(unsigned long long &d,
                                      unsigned long long a,
                                      unsigned long long b) {
    asm("fma.rn.f32x2 %0, %1, %2, %0;" : "+l"(d) : "l"(a), "l"(b));
}
__device__ __forceinline__ float2 unpack2(unsigned long long v) {
    float2 r; asm("mov.b64 {%0, %1}, %2;" : "=f"(r.x), "=f"(r.y) : "l"(v));
    return r;
}

// ---------------- GEMM: C[M,N] = A[M,K] @ W[N,K]^T + bias (+res, +relu) -----
// BM=BN=64, BK=16, 256 threads, 4x4 micro-tile with stride-16 mapping.
// Shared tiles K-contiguous (pitch 18): FFMA2 consumes genuine (k,k+1) pairs.
#define GP 18

template<bool RELU>
__global__ __launch_bounds__(256)
void gemm_nt_kernel(const float* __restrict__ A, const float* __restrict__ W,
                    const float* __restrict__ bias, const float* __restrict__ res,
                    float* __restrict__ C, int M, int N, int K)
{
    __shared__ __align__(16) float As[64*GP];
    __shared__ __align__(16) float Bs[64*GP];

    int tid = threadIdx.x;
    int tx = tid & 15, ty = tid >> 4;
    int bm = blockIdx.y << 6, bn = blockIdx.x << 6;

    int lrow = tid >> 2;          // 0..63
    int lk   = (tid & 3) << 2;    // 0,4,8,12
    const float* Ap = A + (size_t)(bm + lrow) * K + lk;
    const float* Wp = W + (size_t)(bn + lrow) * K + lk;
    float* Asw = &As[lrow*GP + lk];
    float* Bsw = &Bs[lrow*GP + lk];

    unsigned long long acc[4][4];
    #pragma unroll
    for (int i = 0; i < 4; i++)
        #pragma unroll
        for (int j = 0; j < 4; j++) acc[i][j] = 0ull;

    for (int k0 = 0; k0 < K; k0 += 16) {
        float4 av = *(const float4*)(Ap + k0);
        float4 wv = *(const float4*)(Wp + k0);
        __syncthreads();
        *(float2*)(Asw)     = make_float2(av.x, av.y);
        *(float2*)(Asw + 2) = make_float2(av.z, av.w);
        *(float2*)(Bsw)     = make_float2(wv.x, wv.y);
        *(float2*)(Bsw + 2) = make_float2(wv.z, wv.w);
        __syncthreads();
        #pragma unroll
        for (int kp = 0; kp < 8; kp++) {
            int kk = kp * 2;
            unsigned long long a2[4], b2[4];
            #pragma unroll
            for (int i = 0; i < 4; i++)
                a2[i] = *(const unsigned long long*)&As[(ty + i*16)*GP + kk];
            #pragma unroll
            for (int j = 0; j < 4; j++)
                b2[j] = *(const unsigned long long*)&Bs[(tx + j*16)*GP + kk];
            #pragma unroll
            for (int i = 0; i < 4; i++)
                #pragma unroll
                for (int j = 0; j < 4; j++)
                    ffma2(acc[i][j], a2[i], b2[j]);
        }
    }

    #pragma unroll
    for (int i = 0; i < 4; i++) {
        int m = bm + ty + i*16;
        #pragma unroll
        for (int j = 0; j < 4; j++) {
            int n = bn + tx + j*16;
            float2 p = unpack2(acc[i][j]);
            float v = p.x + p.y + bias[n];
            if (res)  v += res[(size_t)m * N + n];
            if (RELU) v = fmaxf(v, 0.0f);
            C[(size_t)m * N + n] = v;
        }
    }
}

// ---------------- banded attention ------------------------------------------
// One block per (b, h, 64-query tile). Key strip = 320 keys [qstart-128, qstart+191].
// Full score strip in SMEM -> exact softmax -> P@V. S stored [key][query].
#define ATT_SMEM ((2*64*68 + 320*68 + 64)*4)  /* 122112 B */

__global__ __launch_bounds__(256)
void attn_kernel(const float* __restrict__ qkv, float* __restrict__ out)
{
    extern __shared__ __align__(16) float sm[];
    float* Qs   = sm;               // [64][68]  Qs[d*68+qi] (transposed)
    float* KVs  = sm + 64*68;       // [64][68]  phase A: K transposed; phase C: V [kj][d]
    float* S    = sm + 2*64*68;     // [320][68] S[kidx*68+qi]
    float* rsum = S + 320*68;       // [64]

    int tid = threadIdx.x;
    int tx = tid & 15, ty = tid >> 4;
    int b = blockIdx.z, h = blockIdx.y;
    int qstart = blockIdx.x << 6;
    size_t rowbase = (size_t)b * Tseq;

    // Load Q tile, transposed to [d][qi]
    #pragma unroll
    for (int r = 0; r < 4; r++) {
        int s  = tid + r*256;       // 0..1023
        int qi = s >> 4;
        int d4 = (s & 15) << 2;
        float4 v = *(const float4*)(qkv + (rowbase + qstart + qi)*1536 + h*64 + d4);
        Qs[(d4+0)*68 + qi] = v.x;
        Qs[(d4+1)*68 + qi] = v.y;
        Qs[(d4+2)*68 + qi] = v.z;
        Qs[(d4+3)*68 + qi] = v.w;
    }

    const float scale = 0.125f;     // 1/sqrt(64)

    // Phase A: scores S[kidx][qi]
    for (int kb = 0; kb < 5; kb++) {
        __syncthreads();
        #pragma unroll
        for (int r = 0; r < 4; r++) {
            int s  = tid + r*256;
            int kj = s >> 4;
            int d4 = (s & 15) << 2;
            int ka = qstart - 128 + kb*64 + kj;
            float4 v = make_float4(0.f, 0.f, 0.f, 0.f);
            if (ka >= 0 && ka < Tseq)
                v = *(const float4*)(qkv + (rowbase + ka)*1536 + 512 + h*64 + d4);
            KVs[(d4+0)*68 + kj] = v.x;
            KVs[(d4+1)*68 + kj] = v.y;
            KVs[(d4+2)*68 + kj] = v.z;
            KVs[(d4+3)*68 + kj] = v.w;
        }
        __syncthreads();
        float acc[4][4] = {};
        #pragma unroll
        for (int d = 0; d < 64; d++) {
            float4 kf = *(const float4*)&KVs[d*68 + ty*4];
            float4 qf = *(const float4*)&Qs [d*68 + tx*4];
            float kv[4] = {kf.x, kf.y, kf.z, kf.w};
            float qv[4] = {qf.x, qf.y, qf.z, qf.w};
            #pragma unroll
            for (int i = 0; i < 4; i++)
                #pragma unroll
                for (int j = 0; j < 4; j++)
                    acc[i][j] += kv[i] * qv[j];
        }
        #pragma unroll
        for (int i = 0; i < 4; i++) {
            int kidx = kb*64 + ty*4 + i;
            int ka   = qstart - 128 + kidx;
            #pragma unroll
            for (int j = 0; j < 4; j++) {
                int qi = tx*4 + j;
                int delta = kidx - qi;      // ka - qa + 128
                bool ok = (delta >= 0) && (delta <= 256) && (ka >= 0) && (ka < Tseq);
                S[kidx*68 + qi] = ok ? acc[i][j] * scale : -1e30f;
            }
        }
    }
    __syncthreads();

    // Phase B: softmax per query (warp w -> queries w*8..w*8+7; 320 = 32 lanes x 10)
    {
        int w = tid >> 5, l = tid & 31;
        for (int q = w*8; q < w*8 + 8; q++) {
            float v[10]; float m = -1e30f;
            #pragma unroll
            for (int i = 0; i < 10; i++) { v[i] = S[(l + i*32)*68 + q]; m = fmaxf(m, v[i]); }
            #pragma unroll
            for (int o = 16; o > 0; o >>= 1) m = fmaxf(m, __shfl_xor_sync(0xffffffffu, m, o));
            float ssum = 0.f;
            #pragma unroll
            for (int i = 0; i < 10; i++) {
                float e = __expf(v[i] - m);
                ssum += e;
                S[(l + i*32)*68 + q] = e;
            }
            #pragma unroll
            for (int o = 16; o > 0; o >>= 1) ssum += __shfl_xor_sync(0xffffffffu, ssum, o);
            if (l == 0) rsum[q] = 1.0f / ssum;
        }
    }

    // Phase C: O = P @ V  (query = ty*4+i, dim = tx*4+j)
    float oacc[4][4] = {};
    for (int kb = 0; kb < 5; kb++) {
        __syncthreads();
        #pragma unroll
        for (int r = 0; r < 4; r++) {
            int s  = tid + r*256;
            int kj = s >> 4;
            int d4 = (s & 15) << 2;
            int ka = qstart - 128 + kb*64 + kj;
            float4 v = make_float4(0.f, 0.f, 0.f, 0.f);
            if (ka >= 0 && ka < Tseq)
                v = *(const float4*)(qkv + (rowbase + ka)*1536 + 1024 + h*64 + d4);
            *(float4*)&KVs[kj*68 + d4] = v;
        }
        __syncthreads();
        #pragma unroll
        for (int kj = 0; kj < 64; kj++) {
            float4 pf = *(const float4*)&S  [(kb*64 + kj)*68 + ty*4];
            float4 vf = *(const float4*)&KVs[kj*68 + tx*4];
            float pv[4] = {pf.x, pf.y, pf.z, pf.w};
            float vv[4] = {vf.x, vf.y, vf.z, vf.w};
            #pragma unroll
            for (int i = 0; i < 4; i++)
                #pragma unroll
                for (int j = 0; j < 4; j++)
                    oacc[i][j] += pv[i] * vv[j];
        }
    }
    #pragma unroll
    for (int i = 0; i < 4; i++) {
        int qi = ty*4 + i;
        float r = rsum[qi];
        float4 o = make_float4(oacc[i][0]*r, oacc[i][1]*r, oacc[i][2]*r, oacc[i][3]*r);
        *(float4*)(out + (rowbase + qstart + qi)*512 + h*64 + tx*4) = o;
    }
}

// ---------------- LayerNorm (one block per row of 512) ----------------------
__global__ __launch_bounds__(256)
void ln_kernel(const float* __restrict__ in, const float* __restrict__ gam,
               const float* __restrict__ bet, float* __restrict__ out)
{
    int row = blockIdx.x, tid = threadIdx.x;
    const float* p = in + (size_t)row * 512;
    float x0 = p[tid], x1 = p[tid + 256];
    float s = x0 + x1, q = x0*x0 + x1*x1;
    #pragma unroll
    for (int o = 16; o > 0; o >>= 1) {
        s += __shfl_xor_sync(0xffffffffu, s, o);
        q += __shfl_xor_sync(0xffffffffu, q, o);
    }
    __shared__ float ss[8], sq[8];
    int w = tid >> 5, l = tid & 31;
    if (l == 0) { ss[w] = s; sq[w] = q; }
    __syncthreads();
    float ts = 0.f, tq = 0.f;
    #pragma unroll
    for (int i = 0; i < 8; i++) { ts += ss[i]; tq += sq[i]; }
    float mean = ts * (1.0f/512.0f);
    float var  = tq * (1.0f/512.0f) - mean*mean;
    float inv  = rsqrtf(var + 1e-5f);
    float* o = out + (size_t)row * 512;
    o[tid]       = (x0 - mean) * inv * gam[tid]       + bet[tid];
    o[tid + 256] = (x1 - mean) * inv * gam[tid + 256] + bet[tid + 256];
}

// ---------------- input projection: x = feat @ proj_w^T + b + pos_enc -------
__global__ __launch_bounds__(128)
void inproj_kernel(const float* __restrict__ feat, const float* __restrict__ w,
                   const float* __restrict__ bias, const float* __restrict__ pe,
                   float* __restrict__ out)
{
    int row = blockIdx.x;
    int t = row & (Tseq - 1);
    __shared__ float f[32];
    if (threadIdx.x < 32) f[threadIdx.x] = feat[(size_t)row*32 + threadIdx.x];
    __syncthreads();
    int d0 = threadIdx.x * 4;
    float a[4];
    #pragma unroll
    for (int j = 0; j < 4; j++) a[j] = bias[d0 + j];
    #pragma unroll
    for (int j = 0; j < 4; j++) {
        const float4* wp = (const float4*)(w + (size_t)(d0 + j) * 32);
        #pragma unroll
        for (int k4 = 0; k4 < 8; k4++) {
            float4 wv = wp[k4];
            a[j] += wv.x*f[k4*4] + wv.y*f[k4*4+1] + wv.z*f[k4*4+2] + wv.w*f[k4*4+3];
        }
    }
    float4 pev = *(const float4*)(pe + (size_t)t*512 + d0);
    float4 r = make_float4(a[0]+pev.x, a[1]+pev.y, a[2]+pev.z, a[3]+pev.w);
    *(float4*)(out + (size_t)row*512 + d0) = r;
}

// ---------------- launch ----------------------------------------------------
extern "C" void kernel_launch(void* const* d_in, const int* in_sizes, int n_in,
                              void* d_out, int out_size)
{
    const float* feat   = (const float*)d_in[0];
    // d_in[1] = positions (unused in eval forward)
    const float* proj_w = (const float*)d_in[2];
    const float* proj_b = (const float*)d_in[3];
    const float* pe     = (const float*)d_in[4];
    const float* qkv_w  = (const float*)d_in[5];
    const float* qkv_b  = (const float*)d_in[6];
    const float* out_w  = (const float*)d_in[7];
    const float* out_b  = (const float*)d_in[8];
    const float* ff1_w  = (const float*)d_in[9];
    const float* ff1_b  = (const float*)d_in[10];
    const float* ff2_w  = (const float*)d_in[11];
    const float* ff2_b  = (const float*)d_in[12];
    const float* ln1_g  = (const float*)d_in[13];
    const float* ln1_b  = (const float*)d_in[14];
    const float* ln2_g  = (const float*)d_in[15];
    const float* ln2_b  = (const float*)d_in[16];

    float *x, *y, *att, *qkv, *ff;
    cudaGetSymbolAddress((void**)&x,   g_x);
    cudaGetSymbolAddress((void**)&y,   g_y);
    cudaGetSymbolAddress((void**)&att, g_att);
    cudaGetSymbolAddress((void**)&qkv, g_qkv);
    cudaGetSymbolAddress((void**)&ff,  g_ff);

    cudaFuncSetAttribute(attn_kernel, cudaFuncAttributeMaxDynamicSharedMemorySize, ATT_SMEM);

    inproj_kernel<<<ROWS, 128>>>(feat, proj_w, proj_b, pe, x);

    dim3 blk(256);
    for (int l = 0; l < NLAYER; l++) {
        // QKV: [8192,512] @ [1536,512]^T
        gemm_nt_kernel<false><<<dim3(1536/64, ROWS/64), blk>>>(
            x, qkv_w + (size_t)l*1536*512, qkv_b + (size_t)l*1536, nullptr,
            qkv, ROWS, 1536, 512);
        // banded attention
        attn_kernel<<<dim3(Tseq/64, Hh, Bsz), blk, ATT_SMEM>>>(qkv, att);
        // out proj + residual(x)
        gemm_nt_kernel<false><<<dim3(512/64, ROWS/64), blk>>>(
            att, out_w + (size_t)l*512*512, out_b + (size_t)l*512, x,
            y, ROWS, 512, 512);
        // LN1 -> x
        ln_kernel<<<ROWS, 256>>>(y, ln1_g + (size_t)l*512, ln1_b + (size_t)l*512, x);
        // FF1 + ReLU
        gemm_nt_kernel<true><<<dim3(2048/64, ROWS/64), blk>>>(
            x, ff1_w + (size_t)l*2048*512, ff1_b + (size_t)l*2048, nullptr,
            ff, ROWS, 2048, 512);
        // FF2 + residual(x)
        gemm_nt_kernel<false><<<dim3(512/64, ROWS/64), blk>>>(
            ff, ff2_w + (size_t)l*512*2048, ff2_b + (size_t)l*512, x,
            y, ROWS, 512, 2048);
        // LN2 -> x (or final output)
        float* lnout = (l == NLAYER - 1) ? (float*)d_out : x;
        ln_kernel<<<ROWS, 256>>>(y, ln2_g + (size_t)l*512, ln2_b + (size_t)l*512, lnout);
    }
}

// round 3
// speedup vs baseline: 2.1475x; 2.1475x over previous
#include <cuda_runtime.h>
#include <cuda_bf16.h>
#include <cstdint>
#include <cstddef>

#define Bsz 4
#define Tseq 2048
#define Dm 512
#define Hh 8
#define FFd 2048
#define NLAYER 4
#define ROWS (Bsz*Tseq)   /* 8192 */

// ---------------- scratch (device globals; no allocations allowed) ----------
__device__ __align__(128) float g_x  [ROWS*Dm];
__device__ __align__(128) float g_y  [ROWS*Dm];
__device__ __align__(128) float g_qkv[ROWS*3*Dm];
__device__ __align__(128) __nv_bfloat16 g_xh[ROWS*Dm],  g_xl[ROWS*Dm];
__device__ __align__(128) __nv_bfloat16 g_ah[ROWS*Dm],  g_al[ROWS*Dm];
__device__ __align__(128) __nv_bfloat16 g_fh[ROWS*FFd], g_fl[ROWS*FFd];
__device__ __align__(128) __nv_bfloat16 g_wqh[NLAYER*3*Dm*Dm], g_wql[NLAYER*3*Dm*Dm];
__device__ __align__(128) __nv_bfloat16 g_woh[NLAYER*Dm*Dm],   g_wol[NLAYER*Dm*Dm];
__device__ __align__(128) __nv_bfloat16 g_w1h[NLAYER*FFd*Dm],  g_w1l[NLAYER*FFd*Dm];
__device__ __align__(128) __nv_bfloat16 g_w2h[NLAYER*Dm*FFd],  g_w2l[NLAYER*Dm*FFd];

// ---------------- helpers ----------------------------------------------------
__device__ __forceinline__ void cp16(uint32_t s, const void* g) {
    asm volatile("cp.async.cg.shared.global [%0], [%1], 16;" :: "r"(s), "l"(g));
}
__device__ __forceinline__ void cp_commit() {
    asm volatile("cp.async.commit_group;" ::: "memory");
}
template<int N> __device__ __forceinline__ void cp_wait() {
    asm volatile("cp.async.wait_group %0;" :: "n"(N) : "memory");
}
__device__ __forceinline__ void ldsm4(uint32_t* r, uint32_t addr) {
    asm volatile("ldmatrix.sync.aligned.m8n8.x4.shared.b16 {%0,%1,%2,%3}, [%4];"
                 : "=r"(r[0]), "=r"(r[1]), "=r"(r[2]), "=r"(r[3]) : "r"(addr));
}
__device__ __forceinline__ void mma16816(float* c, const uint32_t* a, const uint32_t* b) {
    asm volatile(
        "mma.sync.aligned.m16n8k16.row.col.f32.bf16.bf16.f32 "
        "{%0,%1,%2,%3}, {%4,%5,%6,%7}, {%8,%9}, {%0,%1,%2,%3};"
        : "+f"(c[0]), "+f"(c[1]), "+f"(c[2]), "+f"(c[3])
        : "r"(a[0]), "r"(a[1]), "r"(a[2]), "r"(a[3]), "r"(b[0]), "r"(b[1]));
}

__device__ __forceinline__ void split_store4(__nv_bfloat16* __restrict__ H,
                                             __nv_bfloat16* __restrict__ L,
                                             size_t idx, float4 v) {
    __nv_bfloat16 h0 = __float2bfloat16(v.x), h1 = __float2bfloat16(v.y);
    __nv_bfloat16 h2 = __float2bfloat16(v.z), h3 = __float2bfloat16(v.w);
    __nv_bfloat16 l0 = __float2bfloat16(v.x - __bfloat162float(h0));
    __nv_bfloat16 l1 = __float2bfloat16(v.y - __bfloat162float(h1));
    __nv_bfloat16 l2 = __float2bfloat16(v.z - __bfloat162float(h2));
    __nv_bfloat16 l3 = __float2bfloat16(v.w - __bfloat162float(h3));
    union U { __nv_bfloat16 b[4]; uint2 u; };
    U uh, ul;
    uh.b[0] = h0; uh.b[1] = h1; uh.b[2] = h2; uh.b[3] = h3;
    ul.b[0] = l0; ul.b[1] = l1; ul.b[2] = l2; ul.b[3] = l3;
    *(uint2*)(H + idx) = uh.u;
    *(uint2*)(L + idx) = ul.u;
}
__device__ __forceinline__ void split_store1(__nv_bfloat16* H, __nv_bfloat16* L,
                                             size_t idx, float v) {
    __nv_bfloat16 h = __float2bfloat16(v);
    H[idx] = h;
    L[idx] = __float2bfloat16(v - __bfloat162float(h));
}

// ---------------- weight fp32 -> bf16 hi/lo split ----------------------------
__global__ __launch_bounds__(256)
void split4_kernel(const float* __restrict__ w, __nv_bfloat16* __restrict__ h,
                   __nv_bfloat16* __restrict__ l, int n4) {
    int i = blockIdx.x * 256 + threadIdx.x;
    if (i < n4) {
        float4 v = ((const float4*)w)[i];
        split_store4(h, l, (size_t)i * 4, v);
    }
}

// ---------------- HMMA GEMM: C[M,N] = A[M,K] @ W[N,K]^T ----------------------
// bf16x3 into fp32 acc: C = Ah*Bh + Ah*Bl + Al*Bh.
// BM=128, BN=128, BK=32, 256 threads (8 warps, warp tile 64x32), 3-stage cp.async.
// MODE 0: Cf = acc + bias
// MODE 1: Cf = acc + bias + res
// MODE 2: Ch/Cl = split(relu(acc + bias))
#define AROW 80                 /* bytes per smem row (32 bf16 + 16B pad) */
#define TILE_B (128*AROW)       /* 10240 */
#define STAGE_B (4*TILE_B)      /* 40960: Ah, Al, Bh, Bl */
#define NSTAGE 3
#define GS_TOTAL (NSTAGE*STAGE_B)  /* 122880 */

__device__ __forceinline__ void gload(uint32_t st,
    const __nv_bfloat16* __restrict__ Ah, const __nv_bfloat16* __restrict__ Al,
    const __nv_bfloat16* __restrict__ Bh, const __nv_bfloat16* __restrict__ Bl,
    int bm, int bn, int K, int k0, int tid)
{
    #pragma unroll
    for (int i = 0; i < 2; i++) {
        int idx = tid + i * 256;         // 0..511
        int row = idx >> 2, c = idx & 3;
        uint32_t so = (uint32_t)(row * AROW + c * 16);
        size_t go = (size_t)(bm + row) * K + k0 + c * 8;
        cp16(st + so,          Ah + go);
        cp16(st + TILE_B + so, Al + go);
    }
    #pragma unroll
    for (int i = 0; i < 2; i++) {
        int idx = tid + i * 256;
        int row = idx >> 2, c = idx & 3;
        uint32_t so = (uint32_t)(row * AROW + c * 16);
        size_t go = (size_t)(bn + row) * K + k0 + c * 8;
        cp16(st + 2*TILE_B + so, Bh + go);
        cp16(st + 3*TILE_B + so, Bl + go);
    }
    cp_commit();
}

template<int MODE>
__global__ __launch_bounds__(256, 1)
void tc_gemm(const __nv_bfloat16* __restrict__ Ah, const __nv_bfloat16* __restrict__ Al,
             const __nv_bfloat16* __restrict__ Bh, const __nv_bfloat16* __restrict__ Bl,
             const float* __restrict__ bias, const float* __restrict__ res,
             float* __restrict__ Cf, __nv_bfloat16* __restrict__ Ch,
             __nv_bfloat16* __restrict__ Cl, int M, int N, int K)
{
    extern __shared__ __align__(128) char smem[];
    uint32_t sb = (uint32_t)__cvta_generic_to_shared(smem);
    int tid = threadIdx.x;
    int wid = tid >> 5, lane = tid & 31;
    int bn = blockIdx.x * 128, bm = blockIdx.y * 128;
    int wm = (wid >> 2) * 64;     // warp m-offset (0/64)
    int wn = (wid & 3) * 32;      // warp n-offset (0/32/64/96)

    float acc[4][4][4];
    #pragma unroll
    for (int i = 0; i < 4; i++)
        #pragma unroll
        for (int j = 0; j < 4; j++)
            #pragma unroll
            for (int r = 0; r < 4; r++) acc[i][j][r] = 0.f;

    const int C = K >> 5;
    gload(sb,           Ah, Al, Bh, Bl, bm, bn, K, 0,  tid);
    gload(sb + STAGE_B, Ah, Al, Bh, Bl, bm, bn, K, 32, tid);

    // precomputed ldmatrix lane addressing
    uint32_t a_row = (uint32_t)(lane & 15);
    uint32_t a_koff = (uint32_t)((lane >> 4) * 16);        // bytes
    uint32_t b_row = (uint32_t)((lane & 7) + ((lane >> 4) << 3));
    uint32_t b_koff = (uint32_t)(((lane >> 3) & 1) * 16);  // bytes

    for (int c = 0; c < C; c++) {
        if (c + 1 < C) cp_wait<1>(); else cp_wait<0>();
        __syncthreads();
        if (c + 2 < C)
            gload(sb + ((c + 2) % NSTAGE) * STAGE_B, Ah, Al, Bh, Bl, bm, bn, K, (c + 2) * 32, tid);

        uint32_t sa = sb + (c % NSTAGE) * STAGE_B;
        #pragma unroll
        for (int kk = 0; kk < 2; kk++) {          // two k16 steps in BK=32
            uint32_t kb = (uint32_t)(kk * 32);    // byte offset of k-step
            uint32_t af[2][4][4];
            uint32_t bf[2][2][4];
            #pragma unroll
            for (int mt = 0; mt < 4; mt++) {
                uint32_t ad = sa + (wm + mt*16 + a_row) * AROW + kb + a_koff;
                ldsm4(af[0][mt], ad);
                ldsm4(af[1][mt], ad + TILE_B);
            }
            #pragma unroll
            for (int ng = 0; ng < 2; ng++) {
                uint32_t bd = sa + 2*TILE_B + (wn + ng*16 + b_row) * AROW + kb + b_koff;
                ldsm4(bf[0][ng], bd);
                ldsm4(bf[1][ng], bd + TILE_B);
            }
            #pragma unroll
            for (int mt = 0; mt < 4; mt++)
                #pragma unroll
                for (int ng = 0; ng < 2; ng++)
                    #pragma unroll
                    for (int half = 0; half < 2; half++) {
                        int nt = ng*2 + half;
                        mma16816(acc[mt][nt], af[0][mt], &bf[0][ng][half*2]);  // Ah*Bh
                        mma16816(acc[mt][nt], af[0][mt], &bf[1][ng][half*2]);  // Ah*Bl
                        mma16816(acc[mt][nt], af[1][mt], &bf[0][ng][half*2]);  // Al*Bh
                    }
        }
    }

    // epilogue: direct global stores (float2 / bf16x2 pairs)
    #pragma unroll
    for (int mt = 0; mt < 4; mt++) {
        int m0 = bm + wm + mt*16 + (lane >> 2);
        #pragma unroll
        for (int nt = 0; nt < 4; nt++) {
            int n = bn + wn + nt*8 + (lane & 3)*2;
            float bx = bias[n], by = bias[n+1];
            #pragma unroll
            for (int h = 0; h < 2; h++) {
                int m = m0 + h*8;
                float v0 = acc[mt][nt][h*2]   + bx;
                float v1 = acc[mt][nt][h*2+1] + by;
                size_t idx = (size_t)m * N + n;
                if (MODE == 1) {
                    float2 rv = *(const float2*)&res[idx];
                    v0 += rv.x; v1 += rv.y;
                }
                if (MODE == 2) {
                    v0 = fmaxf(v0, 0.f); v1 = fmaxf(v1, 0.f);
                    __nv_bfloat16 h0 = __float2bfloat16(v0);
                    __nv_bfloat16 h1 = __float2bfloat16(v1);
                    __nv_bfloat16 l0 = __float2bfloat16(v0 - __bfloat162float(h0));
                    __nv_bfloat16 l1 = __float2bfloat16(v1 - __bfloat162float(h1));
                    union U { __nv_bfloat16 b[2]; uint32_t u; };
                    U uh, ul;
                    uh.b[0] = h0; uh.b[1] = h1;
                    ul.b[0] = l0; ul.b[1] = l1;
                    *(uint32_t*)(Ch + idx) = uh.u;
                    *(uint32_t*)(Cl + idx) = ul.u;
                } else {
                    *(float2*)&Cf[idx] = make_float2(v0, v1);
                }
            }
        }
    }
}

// ---------------- banded attention ------------------------------------------
#define ATT_SMEM ((2*64*68 + 320*68 + 64)*4)

__global__ __launch_bounds__(256)
void attn_kernel(const float* __restrict__ qkv, __nv_bfloat16* __restrict__ outh,
                 __nv_bfloat16* __restrict__ outl)
{
    extern __shared__ __align__(16) float sm[];
    float* Qs   = sm;
    float* KVs  = sm + 64*68;
    float* S    = sm + 2*64*68;
    float* rsum = S + 320*68;

    int tid = threadIdx.x;
    int tx = tid & 15, ty = tid >> 4;
    int b = blockIdx.z, h = blockIdx.y;
    int qstart = blockIdx.x << 6;
    size_t rowbase = (size_t)b * Tseq;

    #pragma unroll
    for (int r = 0; r < 4; r++) {
        int s  = tid + r*256;
        int qi = s >> 4;
        int d4 = (s & 15) << 2;
        float4 v = *(const float4*)(qkv + (rowbase + qstart + qi)*1536 + h*64 + d4);
        Qs[(d4+0)*68 + qi] = v.x;
        Qs[(d4+1)*68 + qi] = v.y;
        Qs[(d4+2)*68 + qi] = v.z;
        Qs[(d4+3)*68 + qi] = v.w;
    }
    const float scale = 0.125f;

    for (int kb = 0; kb < 5; kb++) {
        __syncthreads();
        #pragma unroll
        for (int r = 0; r < 4; r++) {
            int s  = tid + r*256;
            int kj = s >> 4;
            int d4 = (s & 15) << 2;
            int ka = qstart - 128 + kb*64 + kj;
            float4 v = make_float4(0.f, 0.f, 0.f, 0.f);
            if (ka >= 0 && ka < Tseq)
                v = *(const float4*)(qkv + (rowbase + ka)*1536 + 512 + h*64 + d4);
            KVs[(d4+0)*68 + kj] = v.x;
            KVs[(d4+1)*68 + kj] = v.y;
            KVs[(d4+2)*68 + kj] = v.z;
            KVs[(d4+3)*68 + kj] = v.w;
        }
        __syncthreads();
        float acc[4][4] = {};
        #pragma unroll
        for (int d = 0; d < 64; d++) {
            float4 kf = *(const float4*)&KVs[d*68 + ty*4];
            float4 qf = *(const float4*)&Qs [d*68 + tx*4];
            float kv[4] = {kf.x, kf.y, kf.z, kf.w};
            float qv[4] = {qf.x, qf.y, qf.z, qf.w};
            #pragma unroll
            for (int i = 0; i < 4; i++)
                #pragma unroll
                for (int j = 0; j < 4; j++)
                    acc[i][j] += kv[i] * qv[j];
        }
        #pragma unroll
        for (int i = 0; i < 4; i++) {
            int kidx = kb*64 + ty*4 + i;
            int ka   = qstart - 128 + kidx;
            #pragma unroll
            for (int j = 0; j < 4; j++) {
                int qi = tx*4 + j;
                int delta = kidx - qi;
                bool ok = (delta >= 0) && (delta <= 256) && (ka >= 0) && (ka < Tseq);
                S[kidx*68 + qi] = ok ? acc[i][j] * scale : -1e30f;
            }
        }
    }
    __syncthreads();

    {
        int w = tid >> 5, l = tid & 31;
        for (int q = w*8; q < w*8 + 8; q++) {
            float v[10]; float m = -1e30f;
            #pragma unroll
            for (int i = 0; i < 10; i++) { v[i] = S[(l + i*32)*68 + q]; m = fmaxf(m, v[i]); }
            #pragma unroll
            for (int o = 16; o > 0; o >>= 1) m = fmaxf(m, __shfl_xor_sync(0xffffffffu, m, o));
            float ssum = 0.f;
            #pragma unroll
            for (int i = 0; i < 10; i++) {
                float e = __expf(v[i] - m);
                ssum += e;
                S[(l + i*32)*68 + q] = e;
            }
            #pragma unroll
            for (int o = 16; o > 0; o >>= 1) ssum += __shfl_xor_sync(0xffffffffu, ssum, o);
            if (l == 0) rsum[q] = 1.0f / ssum;
        }
    }

    float oacc[4][4] = {};
    for (int kb = 0; kb < 5; kb++) {
        __syncthreads();
        #pragma unroll
        for (int r = 0; r < 4; r++) {
            int s  = tid + r*256;
            int kj = s >> 4;
            int d4 = (s & 15) << 2;
            int ka = qstart - 128 + kb*64 + kj;
            float4 v = make_float4(0.f, 0.f, 0.f, 0.f);
            if (ka >= 0 && ka < Tseq)
                v = *(const float4*)(qkv + (rowbase + ka)*1536 + 1024 + h*64 + d4);
            *(float4*)&KVs[kj*68 + d4] = v;
        }
        __syncthreads();
        #pragma unroll
        for (int kj = 0; kj < 64; kj++) {
            float4 pf = *(const float4*)&S  [(kb*64 + kj)*68 + ty*4];
            float4 vf = *(const float4*)&KVs[kj*68 + tx*4];
            float pv[4] = {pf.x, pf.y, pf.z, pf.w};
            float vv[4] = {vf.x, vf.y, vf.z, vf.w};
            #pragma unroll
            for (int i = 0; i < 4; i++)
                #pragma unroll
                for (int j = 0; j < 4; j++)
                    oacc[i][j] += pv[i] * vv[j];
        }
    }
    #pragma unroll
    for (int i = 0; i < 4; i++) {
        int qi = ty*4 + i;
        float r = rsum[qi];
        float4 o = make_float4(oacc[i][0]*r, oacc[i][1]*r, oacc[i][2]*r, oacc[i][3]*r);
        split_store4(outh, outl, (rowbase + qstart + qi)*512 + h*64 + tx*4, o);
    }
}

// ---------------- LayerNorm (+ optional bf16 hi/lo output) ------------------
__global__ __launch_bounds__(256)
void ln_kernel(const float* __restrict__ in, const float* __restrict__ gam,
               const float* __restrict__ bet, float* __restrict__ out,
               __nv_bfloat16* __restrict__ oh, __nv_bfloat16* __restrict__ ol)
{
    int row = blockIdx.x, tid = threadIdx.x;
    const float* p = in + (size_t)row * 512;
    float x0 = p[tid], x1 = p[tid + 256];
    float s = x0 + x1, q = x0*x0 + x1*x1;
    #pragma unroll
    for (int o = 16; o > 0; o >>= 1) {
        s += __shfl_xor_sync(0xffffffffu, s, o);
        q += __shfl_xor_sync(0xffffffffu, q, o);
    }
    __shared__ float ss[8], sq[8];
    int w = tid >> 5, l = tid & 31;
    if (l == 0) { ss[w] = s; sq[w] = q; }
    __syncthreads();
    float ts = 0.f, tq = 0.f;
    #pragma unroll
    for (int i = 0; i < 8; i++) { ts += ss[i]; tq += sq[i]; }
    float mean = ts * (1.0f/512.0f);
    float var  = tq * (1.0f/512.0f) - mean*mean;
    float inv  = rsqrtf(var + 1e-5f);
    float v0 = (x0 - mean) * inv * gam[tid]       + bet[tid];
    float v1 = (x1 - mean) * inv * gam[tid + 256] + bet[tid + 256];
    float* o = out + (size_t)row * 512;
    o[tid]       = v0;
    o[tid + 256] = v1;
    if (oh) {
        split_store1(oh, ol, (size_t)row*512 + tid,       v0);
        split_store1(oh, ol, (size_t)row*512 + tid + 256, v1);
    }
}

// ---------------- input projection ------------------------------------------
__global__ __launch_bounds__(128)
void inproj_kernel(const float* __restrict__ feat, const float* __restrict__ w,
                   const float* __restrict__ bias, const float* __restrict__ pe,
                   float* __restrict__ out, __nv_bfloat16* __restrict__ oh,
                   __nv_bfloat16* __restrict__ ol)
{
    int row = blockIdx.x;
    int t = row & (Tseq - 1);
    __shared__ float f[32];
    if (threadIdx.x < 32) f[threadIdx.x] = feat[(size_t)row*32 + threadIdx.x];
    __syncthreads();
    int d0 = threadIdx.x * 4;
    float a[4];
    #pragma unroll
    for (int j = 0; j < 4; j++) a[j] = bias[d0 + j];
    #pragma unroll
    for (int j = 0; j < 4; j++) {
        const float4* wp = (const float4*)(w + (size_t)(d0 + j) * 32);
        #pragma unroll
        for (int k4 = 0; k4 < 8; k4++) {
            float4 wv = wp[k4];
            a[j] += wv.x*f[k4*4] + wv.y*f[k4*4+1] + wv.z*f[k4*4+2] + wv.w*f[k4*4+3];
        }
    }
    float4 pev = *(const float4*)(pe + (size_t)t*512 + d0);
    float4 r = make_float4(a[0]+pev.x, a[1]+pev.y, a[2]+pev.z, a[3]+pev.w);
    *(float4*)(out + (size_t)row*512 + d0) = r;
    split_store4(oh, ol, (size_t)row*512 + d0, r);
}

// ---------------- launch ----------------------------------------------------
extern "C" void kernel_launch(void* const* d_in, const int* in_sizes, int n_in,
                              void* d_out, int out_size)
{
    const float* feat   = (const float*)d_in[0];
    const float* proj_w = (const float*)d_in[2];
    const float* proj_b = (const float*)d_in[3];
    const float* pe     = (const float*)d_in[4];
    const float* qkv_w  = (const float*)d_in[5];
    const float* qkv_b  = (const float*)d_in[6];
    const float* out_w  = (const float*)d_in[7];
    const float* out_b  = (const float*)d_in[8];
    const float* ff1_w  = (const float*)d_in[9];
    const float* ff1_b  = (const float*)d_in[10];
    const float* ff2_w  = (const float*)d_in[11];
    const float* ff2_b  = (const float*)d_in[12];
    const float* ln1_g  = (const float*)d_in[13];
    const float* ln1_b  = (const float*)d_in[14];
    const float* ln2_g  = (const float*)d_in[15];
    const float* ln2_b  = (const float*)d_in[16];

    float *x, *y, *qkv;
    __nv_bfloat16 *xh, *xl, *ah, *al, *fh, *fl;
    __nv_bfloat16 *wqh, *wql, *woh, *wol, *w1h, *w1l, *w2h, *w2l;
    cudaGetSymbolAddress((void**)&x,   g_x);
    cudaGetSymbolAddress((void**)&y,   g_y);
    cudaGetSymbolAddress((void**)&qkv, g_qkv);
    cudaGetSymbolAddress((void**)&xh,  g_xh);  cudaGetSymbolAddress((void**)&xl, g_xl);
    cudaGetSymbolAddress((void**)&ah,  g_ah);  cudaGetSymbolAddress((void**)&al, g_al);
    cudaGetSymbolAddress((void**)&fh,  g_fh);  cudaGetSymbolAddress((void**)&fl, g_fl);
    cudaGetSymbolAddress((void**)&wqh, g_wqh); cudaGetSymbolAddress((void**)&wql, g_wql);
    cudaGetSymbolAddress((void**)&woh, g_woh); cudaGetSymbolAddress((void**)&wol, g_wol);
    cudaGetSymbolAddress((void**)&w1h, g_w1h); cudaGetSymbolAddress((void**)&w1l, g_w1l);
    cudaGetSymbolAddress((void**)&w2h, g_w2h); cudaGetSymbolAddress((void**)&w2l, g_w2l);

    cudaFuncSetAttribute(attn_kernel, cudaFuncAttributeMaxDynamicSharedMemorySize, ATT_SMEM);
    cudaFuncSetAttribute(tc_gemm<0>, cudaFuncAttributeMaxDynamicSharedMemorySize, GS_TOTAL);
    cudaFuncSetAttribute(tc_gemm<1>, cudaFuncAttributeMaxDynamicSharedMemorySize, GS_TOTAL);
    cudaFuncSetAttribute(tc_gemm<2>, cudaFuncAttributeMaxDynamicSharedMemorySize, GS_TOTAL);

    // weight splits (fp32 -> bf16 hi/lo)
    {
        int n4;
        n4 = NLAYER*3*Dm*Dm/4; split4_kernel<<<(n4+255)/256,256>>>(qkv_w, wqh, wql, n4);
        n4 = NLAYER*Dm*Dm/4;   split4_kernel<<<(n4+255)/256,256>>>(out_w, woh, wol, n4);
        n4 = NLAYER*FFd*Dm/4;  split4_kernel<<<(n4+255)/256,256>>>(ff1_w, w1h, w1l, n4);
        n4 = NLAYER*Dm*FFd/4;  split4_kernel<<<(n4+255)/256,256>>>(ff2_w, w2h, w2l, n4);
    }

    inproj_kernel<<<ROWS, 128>>>(feat, proj_w, proj_b, pe, x, xh, xl);

    for (int l = 0; l < NLAYER; l++) {
        // QKV: [8192,1536] = x @ qkv_w^T
        tc_gemm<0><<<dim3(3*Dm/128, ROWS/128), 256, GS_TOTAL>>>(
            xh, xl, wqh + (size_t)l*3*Dm*Dm, wql + (size_t)l*3*Dm*Dm,
            qkv_b + (size_t)l*3*Dm, nullptr, qkv, nullptr, nullptr,
            ROWS, 3*Dm, Dm);
        // banded attention -> (ah, al)
        attn_kernel<<<dim3(Tseq/64, Hh, Bsz), 256, ATT_SMEM>>>(qkv, ah, al);
        // out proj + residual(x) -> y
        tc_gemm<1><<<dim3(Dm/128, ROWS/128), 256, GS_TOTAL>>>(
            ah, al, woh + (size_t)l*Dm*Dm, wol + (size_t)l*Dm*Dm,
            out_b + (size_t)l*Dm, x, y, nullptr, nullptr,
            ROWS, Dm, Dm);
        // LN1 -> x (+ hi/lo)
        ln_kernel<<<ROWS, 256>>>(y, ln1_g + (size_t)l*Dm, ln1_b + (size_t)l*Dm, x, xh, xl);
        // FF1 + ReLU -> (fh, fl)
        tc_gemm<2><<<dim3(FFd/128, ROWS/128), 256, GS_TOTAL>>>(
            xh, xl, w1h + (size_t)l*FFd*Dm, w1l + (size_t)l*FFd*Dm,
            ff1_b + (size_t)l*FFd, nullptr, nullptr, fh, fl,
            ROWS, FFd, Dm);
        // FF2 + residual(x) -> y
        tc_gemm<1><<<dim3(Dm/128, ROWS/128), 256, GS_TOTAL>>>(
            fh, fl, w2h + (size_t)l*Dm*FFd, w2l + (size_t)l*Dm*FFd,
            ff2_b + (size_t)l*Dm, x, y, nullptr, nullptr,
            ROWS, Dm, FFd);
        // LN2 -> x (or final output)
        if (l == NLAYER - 1)
            ln_kernel<<<ROWS, 256>>>(y, ln2_g + (size_t)l*Dm, ln2_b + (size_t)l*Dm,
                                     (float*)d_out, nullptr, nullptr);
        else
            ln_kernel<<<ROWS, 256>>>(y, ln2_g + (size_t)l*Dm, ln2_b + (size_t)l*Dm, x, xh, xl);
    }
}

// round 4
// speedup vs baseline: 2.1503x; 1.0013x over previous
#include <cuda_runtime.h>
#include <cuda_bf16.h>
#include <cstdint>
#include <cstddef>

#define Bsz 4
#define Tseq 2048
#define Dm 512
#define Hh 8
#define FFd 2048
#define NLAYER 4
#define ROWS (Bsz*Tseq)   /* 8192 */

// ---------------- scratch (device globals; no allocations allowed) ----------
__device__ __align__(128) float g_x  [ROWS*Dm];
__device__ __align__(128) float g_y  [ROWS*Dm];
__device__ __align__(128) float g_qkv[ROWS*3*Dm];
__device__ __align__(128) __nv_bfloat16 g_xh[ROWS*Dm],  g_xl[ROWS*Dm];
__device__ __align__(128) __nv_bfloat16 g_ah[ROWS*Dm],  g_al[ROWS*Dm];
__device__ __align__(128) __nv_bfloat16 g_fh[ROWS*FFd], g_fl[ROWS*FFd];
__device__ __align__(128) __nv_bfloat16 g_wqh[NLAYER*3*Dm*Dm], g_wql[NLAYER*3*Dm*Dm];
__device__ __align__(128) __nv_bfloat16 g_woh[NLAYER*Dm*Dm],   g_wol[NLAYER*Dm*Dm];
__device__ __align__(128) __nv_bfloat16 g_w1h[NLAYER*FFd*Dm],  g_w1l[NLAYER*FFd*Dm];
__device__ __align__(128) __nv_bfloat16 g_w2h[NLAYER*Dm*FFd],  g_w2l[NLAYER*Dm*FFd];

// ---------------- helpers ----------------------------------------------------
__device__ __forceinline__ void cp16(uint32_t s, const void* g) {
    asm volatile("cp.async.cg.shared.global [%0], [%1], 16;" :: "r"(s), "l"(g));
}
__device__ __forceinline__ void cp_commit() {
    asm volatile("cp.async.commit_group;" ::: "memory");
}
template<int N> __device__ __forceinline__ void cp_wait() {
    asm volatile("cp.async.wait_group %0;" :: "n"(N) : "memory");
}
__device__ __forceinline__ void ldsm4(uint32_t* r, uint32_t addr) {
    asm volatile("ldmatrix.sync.aligned.m8n8.x4.shared.b16 {%0,%1,%2,%3}, [%4];"
                 : "=r"(r[0]), "=r"(r[1]), "=r"(r[2]), "=r"(r[3]) : "r"(addr));
}
__device__ __forceinline__ void mma16816(float* c, const uint32_t* a, const uint32_t* b) {
    asm volatile(
        "mma.sync.aligned.m16n8k16.row.col.f32.bf16.bf16.f32 "
        "{%0,%1,%2,%3}, {%4,%5,%6,%7}, {%8,%9}, {%0,%1,%2,%3};"
        : "+f"(c[0]), "+f"(c[1]), "+f"(c[2]), "+f"(c[3])
        : "r"(a[0]), "r"(a[1]), "r"(a[2]), "r"(a[3]), "r"(b[0]), "r"(b[1]));
}
__device__ __forceinline__ void ffma2(unsigned long long &d,
                                      unsigned long long a,
                                      unsigned long long b) {
    asm("fma.rn.f32x2 %0, %1, %2, %0;" : "+l"(d) : "l"(a), "l"(b));
}
__device__ __forceinline__ float2 unpack2(unsigned long long v) {
    float2 r; asm("mov.b64 {%0, %1}, %2;" : "=f"(r.x), "=f"(r.y) : "l"(v));
    return r;
}

__device__ __forceinline__ void split_store4(__nv_bfloat16* __restrict__ H,
                                             __nv_bfloat16* __restrict__ L,
                                             size_t idx, float4 v) {
    __nv_bfloat16 h0 = __float2bfloat16(v.x), h1 = __float2bfloat16(v.y);
    __nv_bfloat16 h2 = __float2bfloat16(v.z), h3 = __float2bfloat16(v.w);
    __nv_bfloat16 l0 = __float2bfloat16(v.x - __bfloat162float(h0));
    __nv_bfloat16 l1 = __float2bfloat16(v.y - __bfloat162float(h1));
    __nv_bfloat16 l2 = __float2bfloat16(v.z - __bfloat162float(h2));
    __nv_bfloat16 l3 = __float2bfloat16(v.w - __bfloat162float(h3));
    union U { __nv_bfloat16 b[4]; uint2 u; };
    U uh, ul;
    uh.b[0] = h0; uh.b[1] = h1; uh.b[2] = h2; uh.b[3] = h3;
    ul.b[0] = l0; ul.b[1] = l1; ul.b[2] = l2; ul.b[3] = l3;
    *(uint2*)(H + idx) = uh.u;
    *(uint2*)(L + idx) = ul.u;
}
__device__ __forceinline__ void split_store1(__nv_bfloat16* H, __nv_bfloat16* L,
                                             size_t idx, float v) {
    __nv_bfloat16 h = __float2bfloat16(v);
    H[idx] = h;
    L[idx] = __float2bfloat16(v - __bfloat162float(h));
}

// ---------------- weight fp32 -> bf16 hi/lo split ----------------------------
__global__ __launch_bounds__(256)
void split4_kernel(const float* __restrict__ w, __nv_bfloat16* __restrict__ h,
                   __nv_bfloat16* __restrict__ l, int n4) {
    int i = blockIdx.x * 256 + threadIdx.x;
    if (i < n4) {
        float4 v = ((const float4*)w)[i];
        split_store4(h, l, (size_t)i * 4, v);
    }
}

// ---------------- HMMA GEMM: C[M,N] = A[M,K] @ W[N,K]^T ----------------------
// bf16x3 into fp32 acc: C = Ah*Bh + Ah*Bl + Al*Bh.
// BM=128, BN=128, BK=32, 256 threads (8 warps, warp tile 64x32), 3-stage cp.async.
#define AROW 80
#define TILE_B (128*AROW)
#define STAGE_B (4*TILE_B)
#define NSTAGE 3
#define GS_TOTAL (NSTAGE*STAGE_B)

__device__ __forceinline__ void gload(uint32_t st,
    const __nv_bfloat16* __restrict__ Ah, const __nv_bfloat16* __restrict__ Al,
    const __nv_bfloat16* __restrict__ Bh, const __nv_bfloat16* __restrict__ Bl,
    int bm, int bn, int K, int k0, int tid)
{
    #pragma unroll
    for (int i = 0; i < 2; i++) {
        int idx = tid + i * 256;
        int row = idx >> 2, c = idx & 3;
        uint32_t so = (uint32_t)(row * AROW + c * 16);
        size_t go = (size_t)(bm + row) * K + k0 + c * 8;
        cp16(st + so,          Ah + go);
        cp16(st + TILE_B + so, Al + go);
    }
    #pragma unroll
    for (int i = 0; i < 2; i++) {
        int idx = tid + i * 256;
        int row = idx >> 2, c = idx & 3;
        uint32_t so = (uint32_t)(row * AROW + c * 16);
        size_t go = (size_t)(bn + row) * K + k0 + c * 8;
        cp16(st + 2*TILE_B + so, Bh + go);
        cp16(st + 3*TILE_B + so, Bl + go);
    }
    cp_commit();
}

template<int MODE>
__global__ __launch_bounds__(256, 1)
void tc_gemm(const __nv_bfloat16* __restrict__ Ah, const __nv_bfloat16* __restrict__ Al,
             const __nv_bfloat16* __restrict__ Bh, const __nv_bfloat16* __restrict__ Bl,
             const float* __restrict__ bias, const float* __restrict__ res,
             float* __restrict__ Cf, __nv_bfloat16* __restrict__ Ch,
             __nv_bfloat16* __restrict__ Cl, int M, int N, int K)
{
    extern __shared__ __align__(128) char smem[];
    uint32_t sb = (uint32_t)__cvta_generic_to_shared(smem);
    int tid = threadIdx.x;
    int wid = tid >> 5, lane = tid & 31;
    int bn = blockIdx.x * 128, bm = blockIdx.y * 128;
    int wm = (wid >> 2) * 64;
    int wn = (wid & 3) * 32;

    float acc[4][4][4];
    #pragma unroll
    for (int i = 0; i < 4; i++)
        #pragma unroll
        for (int j = 0; j < 4; j++)
            #pragma unroll
            for (int r = 0; r < 4; r++) acc[i][j][r] = 0.f;

    const int C = K >> 5;
    gload(sb,           Ah, Al, Bh, Bl, bm, bn, K, 0,  tid);
    gload(sb + STAGE_B, Ah, Al, Bh, Bl, bm, bn, K, 32, tid);

    uint32_t a_row = (uint32_t)(lane & 15);
    uint32_t a_koff = (uint32_t)((lane >> 4) * 16);
    uint32_t b_row = (uint32_t)((lane & 7) + ((lane >> 4) << 3));
    uint32_t b_koff = (uint32_t)(((lane >> 3) & 1) * 16);

    for (int c = 0; c < C; c++) {
        if (c + 1 < C) cp_wait<1>(); else cp_wait<0>();
        __syncthreads();
        if (c + 2 < C)
            gload(sb + ((c + 2) % NSTAGE) * STAGE_B, Ah, Al, Bh, Bl, bm, bn, K, (c + 2) * 32, tid);

        uint32_t sa = sb + (c % NSTAGE) * STAGE_B;
        #pragma unroll
        for (int kk = 0; kk < 2; kk++) {
            uint32_t kb = (uint32_t)(kk * 32);
            uint32_t af[2][4][4];
            uint32_t bf[2][2][4];
            #pragma unroll
            for (int mt = 0; mt < 4; mt++) {
                uint32_t ad = sa + (wm + mt*16 + a_row) * AROW + kb + a_koff;
                ldsm4(af[0][mt], ad);
                ldsm4(af[1][mt], ad + TILE_B);
            }
            #pragma unroll
            for (int ng = 0; ng < 2; ng++) {
                uint32_t bd = sa + 2*TILE_B + (wn + ng*16 + b_row) * AROW + kb + b_koff;
                ldsm4(bf[0][ng], bd);
                ldsm4(bf[1][ng], bd + TILE_B);
            }
            #pragma unroll
            for (int mt = 0; mt < 4; mt++)
                #pragma unroll
                for (int ng = 0; ng < 2; ng++)
                    #pragma unroll
                    for (int half = 0; half < 2; half++) {
                        int nt = ng*2 + half;
                        mma16816(acc[mt][nt], af[0][mt], &bf[0][ng][half*2]);
                        mma16816(acc[mt][nt], af[0][mt], &bf[1][ng][half*2]);
                        mma16816(acc[mt][nt], af[1][mt], &bf[0][ng][half*2]);
                    }
        }
    }

    #pragma unroll
    for (int mt = 0; mt < 4; mt++) {
        int m0 = bm + wm + mt*16 + (lane >> 2);
        #pragma unroll
        for (int nt = 0; nt < 4; nt++) {
            int n = bn + wn + nt*8 + (lane & 3)*2;
            float bx = bias[n], by = bias[n+1];
            #pragma unroll
            for (int h = 0; h < 2; h++) {
                int m = m0 + h*8;
                float v0 = acc[mt][nt][h*2]   + bx;
                float v1 = acc[mt][nt][h*2+1] + by;
                size_t idx = (size_t)m * N + n;
                if (MODE == 1) {
                    float2 rv = *(const float2*)&res[idx];
                    v0 += rv.x; v1 += rv.y;
                }
                if (MODE == 2) {
                    v0 = fmaxf(v0, 0.f); v1 = fmaxf(v1, 0.f);
                    __nv_bfloat16 h0 = __float2bfloat16(v0);
                    __nv_bfloat16 h1 = __float2bfloat16(v1);
                    __nv_bfloat16 l0 = __float2bfloat16(v0 - __bfloat162float(h0));
                    __nv_bfloat16 l1 = __float2bfloat16(v1 - __bfloat162float(h1));
                    union U { __nv_bfloat16 b[2]; uint32_t u; };
                    U uh, ul;
                    uh.b[0] = h0; uh.b[1] = h1;
                    ul.b[0] = l0; ul.b[1] = l1;
                    *(uint32_t*)(Ch + idx) = uh.u;
                    *(uint32_t*)(Cl + idx) = ul.u;
                } else {
                    *(float2*)&Cf[idx] = make_float2(v0, v1);
                }
            }
        }
    }
}

// ---------------- banded attention (FFMA2, swizzled row-major tiles) ---------
// Layouts:
//   Qs[64 q][64 d]  : pair (d>>1) stored at word q*64 + 2*((d>>1) ^ (q>>2)) + (d&1)
//   KV [64 r][64 c] : same swizzle; K rows (phase A) / V^T rows=d (phase C)
//   S  [64 q][328 k]: q-major scores / probabilities
#define SP 328
#define ATT_SMEM ((64*64 + 64*64 + 64*SP + 64)*4)   /* 116,992 B */

__global__ __launch_bounds__(256)
void attn_kernel(const float* __restrict__ qkv, __nv_bfloat16* __restrict__ outh,
                 __nv_bfloat16* __restrict__ outl)
{
    extern __shared__ __align__(16) float sm[];
    float* Qs   = sm;             // 4096 floats
    float* KV   = sm + 4096;      // 4096 floats
    float* S    = sm + 8192;      // 64*328 floats
    float* rsum = S + 64*SP;      // 64

    int tid = threadIdx.x;
    int tx = tid & 15, ty = tid >> 4;
    int b = blockIdx.z, h = blockIdx.y;
    int qstart = blockIdx.x << 6;
    size_t rowbase = (size_t)b * Tseq;

    // ---- load Q tile (row-major, swizzled) ----
    #pragma unroll
    for (int r = 0; r < 4; r++) {
        int s  = tid + r*256;
        int qi = s >> 4;
        int c0 = (s & 15) * 2;                 // pair index of first pair
        int d4 = (s & 15) << 2;
        float4 v = *(const float4*)(qkv + (rowbase + qstart + qi)*1536 + h*64 + d4);
        int sw = qi >> 2;
        *(float2*)&Qs[qi*64 + 2*(c0 ^ sw)]       = make_float2(v.x, v.y);
        *(float2*)&Qs[qi*64 + 2*((c0+1) ^ sw)]   = make_float2(v.z, v.w);
    }
    const float scale = 0.125f;

    // ---- phase A: S[q][k] = Q.K^T (FFMA2 over d-pairs) ----
    for (int kb = 0; kb < 5; kb++) {
        __syncthreads();
        #pragma unroll
        for (int r = 0; r < 4; r++) {
            int s  = tid + r*256;
            int kj = s >> 4;
            int c0 = (s & 15) * 2;
            int d4 = (s & 15) << 2;
            int ka = qstart - 128 + kb*64 + kj;
            float4 v = make_float4(0.f, 0.f, 0.f, 0.f);
            if (ka >= 0 && ka < Tseq)
                v = *(const float4*)(qkv + (rowbase + ka)*1536 + 512 + h*64 + d4);
            int sw = kj >> 2;
            *(float2*)&KV[kj*64 + 2*(c0 ^ sw)]     = make_float2(v.x, v.y);
            *(float2*)&KV[kj*64 + 2*((c0+1) ^ sw)] = make_float2(v.z, v.w);
        }
        __syncthreads();

        unsigned long long acc2[4][4];
        #pragma unroll
        for (int i = 0; i < 4; i++)
            #pragma unroll
            for (int j = 0; j < 4; j++) acc2[i][j] = 0ull;

        #pragma unroll 4
        for (int dp = 0; dp < 32; dp++) {
            unsigned long long q2[4], k2[4];
            #pragma unroll
            for (int i = 0; i < 4; i++)
                q2[i] = *(const unsigned long long*)&Qs[(ty*4+i)*64 + 2*(dp ^ ty)];
            #pragma unroll
            for (int j = 0; j < 4; j++)
                k2[j] = *(const unsigned long long*)&KV[(tx*4+j)*64 + 2*(dp ^ tx)];
            #pragma unroll
            for (int i = 0; i < 4; i++)
                #pragma unroll
                for (int j = 0; j < 4; j++)
                    ffma2(acc2[i][j], q2[i], k2[j]);
        }

        #pragma unroll
        for (int i = 0; i < 4; i++) {
            int qi = ty*4 + i;
            float sv[4];
            #pragma unroll
            for (int j = 0; j < 4; j++) {
                int kidx = kb*64 + tx*4 + j;
                int ka   = qstart - 128 + kidx;
                int delta = kidx - qi;
                float2 p = unpack2(acc2[i][j]);
                bool ok = (delta >= 0) && (delta <= 256) && (ka >= 0) && (ka < Tseq);
                sv[j] = ok ? (p.x + p.y) * scale : -1e30f;
            }
            *(float4*)&S[qi*SP + kb*64 + tx*4] = make_float4(sv[0], sv[1], sv[2], sv[3]);
        }
    }
    __syncthreads();

    // ---- softmax per query (warp w -> queries w*8..w*8+7) ----
    {
        int w = tid >> 5, l = tid & 31;
        for (int q = w*8; q < w*8 + 8; q++) {
            float v[10]; float m = -1e30f;
            #pragma unroll
            for (int i = 0; i < 10; i++) { v[i] = S[q*SP + l + i*32]; m = fmaxf(m, v[i]); }
            #pragma unroll
            for (int o = 16; o > 0; o >>= 1) m = fmaxf(m, __shfl_xor_sync(0xffffffffu, m, o));
            float ssum = 0.f;
            #pragma unroll
            for (int i = 0; i < 10; i++) {
                float e = __expf(v[i] - m);
                ssum += e;
                S[q*SP + l + i*32] = e;
            }
            #pragma unroll
            for (int o = 16; o > 0; o >>= 1) ssum += __shfl_xor_sync(0xffffffffu, ssum, o);
            if (l == 0) rsum[q] = 1.0f / ssum;
        }
    }

    // ---- phase C: O = P @ V (FFMA2 over k-pairs) ----
    unsigned long long oacc2[4][4];
    #pragma unroll
    for (int i = 0; i < 4; i++)
        #pragma unroll
        for (int j = 0; j < 4; j++) oacc2[i][j] = 0ull;

    for (int kb = 0; kb < 5; kb++) {
        __syncthreads();
        #pragma unroll
        for (int r = 0; r < 4; r++) {
            int s  = tid + r*256;
            int kj = s >> 4;
            int d4 = (s & 15) << 2;
            int ka = qstart - 128 + kb*64 + kj;
            float4 v = make_float4(0.f, 0.f, 0.f, 0.f);
            if (ka >= 0 && ka < Tseq)
                v = *(const float4*)(qkv + (rowbase + ka)*1536 + 1024 + h*64 + d4);
            float vv[4] = {v.x, v.y, v.z, v.w};
            #pragma unroll
            for (int jj = 0; jj < 4; jj++) {
                int d = d4 + jj;
                KV[d*64 + 2*((kj>>1) ^ (d>>2)) + (kj&1)] = vv[jj];
            }
        }
        __syncthreads();

        #pragma unroll 4
        for (int kp = 0; kp < 32; kp++) {
            unsigned long long p2[4], v2[4];
            #pragma unroll
            for (int i = 0; i < 4; i++)
                p2[i] = *(const unsigned long long*)&S[(ty*4+i)*SP + kb*64 + 2*kp];
            #pragma unroll
            for (int j = 0; j < 4; j++)
                v2[j] = *(const unsigned long long*)&KV[(tx*4+j)*64 + 2*(kp ^ tx)];
            #pragma unroll
            for (int i = 0; i < 4; i++)
                #pragma unroll
                for (int j = 0; j < 4; j++)
                    ffma2(oacc2[i][j], p2[i], v2[j]);
        }
    }

    #pragma unroll
    for (int i = 0; i < 4; i++) {
        int qi = ty*4 + i;
        float r = rsum[qi];
        float o[4];
        #pragma unroll
        for (int j = 0; j < 4; j++) {
            float2 p = unpack2(oacc2[i][j]);
            o[j] = (p.x + p.y) * r;
        }
        split_store4(outh, outl, (rowbase + qstart + qi)*512 + h*64 + tx*4,
                     make_float4(o[0], o[1], o[2], o[3]));
    }
}

// ---------------- LayerNorm (+ optional bf16 hi/lo output) ------------------
__global__ __launch_bounds__(256)
void ln_kernel(const float* __restrict__ in, const float* __restrict__ gam,
               const float* __restrict__ bet, float* __restrict__ out,
               __nv_bfloat16* __restrict__ oh, __nv_bfloat16* __restrict__ ol)
{
    int row = blockIdx.x, tid = threadIdx.x;
    const float* p = in + (size_t)row * 512;
    float x0 = p[tid], x1 = p[tid + 256];
    float s = x0 + x1, q = x0*x0 + x1*x1;
    #pragma unroll
    for (int o = 16; o > 0; o >>= 1) {
        s += __shfl_xor_sync(0xffffffffu, s, o);
        q += __shfl_xor_sync(0xffffffffu, q, o);
    }
    __shared__ float ss[8], sq[8];
    int w = tid >> 5, l = tid & 31;
    if (l == 0) { ss[w] = s; sq[w] = q; }
    __syncthreads();
    float ts = 0.f, tq = 0.f;
    #pragma unroll
    for (int i = 0; i < 8; i++) { ts += ss[i]; tq += sq[i]; }
    float mean = ts * (1.0f/512.0f);
    float var  = tq * (1.0f/512.0f) - mean*mean;
    float inv  = rsqrtf(var + 1e-5f);
    float v0 = (x0 - mean) * inv * gam[tid]       + bet[tid];
    float v1 = (x1 - mean) * inv * gam[tid + 256] + bet[tid + 256];
    float* o = out + (size_t)row * 512;
    o[tid]       = v0;
    o[tid + 256] = v1;
    if (oh) {
        split_store1(oh, ol, (size_t)row*512 + tid,       v0);
        split_store1(oh, ol, (size_t)row*512 + tid + 256, v1);
    }
}

// ---------------- input projection ------------------------------------------
__global__ __launch_bounds__(128)
void inproj_kernel(const float* __restrict__ feat, const float* __restrict__ w,
                   const float* __restrict__ bias, const float* __restrict__ pe,
                   float* __restrict__ out, __nv_bfloat16* __restrict__ oh,
                   __nv_bfloat16* __restrict__ ol)
{
    int row = blockIdx.x;
    int t = row & (Tseq - 1);
    __shared__ float f[32];
    if (threadIdx.x < 32) f[threadIdx.x] = feat[(size_t)row*32 + threadIdx.x];
    __syncthreads();
    int d0 = threadIdx.x * 4;
    float a[4];
    #pragma unroll
    for (int j = 0; j < 4; j++) a[j] = bias[d0 + j];
    #pragma unroll
    for (int j = 0; j < 4; j++) {
        const float4* wp = (const float4*)(w + (size_t)(d0 + j) * 32);
        #pragma unroll
        for (int k4 = 0; k4 < 8; k4++) {
            float4 wv = wp[k4];
            a[j] += wv.x*f[k4*4] + wv.y*f[k4*4+1] + wv.z*f[k4*4+2] + wv.w*f[k4*4+3];
        }
    }
    float4 pev = *(const float4*)(pe + (size_t)t*512 + d0);
    float4 r = make_float4(a[0]+pev.x, a[1]+pev.y, a[2]+pev.z, a[3]+pev.w);
    *(float4*)(out + (size_t)row*512 + d0) = r;
    split_store4(oh, ol, (size_t)row*512 + d0, r);
}

// ---------------- launch ----------------------------------------------------
extern "C" void kernel_launch(void* const* d_in, const int* in_sizes, int n_in,
                              void* d_out, int out_size)
{
    const float* feat   = (const float*)d_in[0];
    const float* proj_w = (const float*)d_in[2];
    const float* proj_b = (const float*)d_in[3];
    const float* pe     = (const float*)d_in[4];
    const float* qkv_w  = (const float*)d_in[5];
    const float* qkv_b  = (const float*)d_in[6];
    const float* out_w  = (const float*)d_in[7];
    const float* out_b  = (const float*)d_in[8];
    const float* ff1_w  = (const float*)d_in[9];
    const float* ff1_b  = (const float*)d_in[10];
    const float* ff2_w  = (const float*)d_in[11];
    const float* ff2_b  = (const float*)d_in[12];
    const float* ln1_g  = (const float*)d_in[13];
    const float* ln1_b  = (const float*)d_in[14];
    const float* ln2_g  = (const float*)d_in[15];
    const float* ln2_b  = (const float*)d_in[16];

    float *x, *y, *qkv;
    __nv_bfloat16 *xh, *xl, *ah, *al, *fh, *fl;
    __nv_bfloat16 *wqh, *wql, *woh, *wol, *w1h, *w1l, *w2h, *w2l;
    cudaGetSymbolAddress((void**)&x,   g_x);
    cudaGetSymbolAddress((void**)&y,   g_y);
    cudaGetSymbolAddress((void**)&qkv, g_qkv);
    cudaGetSymbolAddress((void**)&xh,  g_xh);  cudaGetSymbolAddress((void**)&xl, g_xl);
    cudaGetSymbolAddress((void**)&ah,  g_ah);  cudaGetSymbolAddress((void**)&al, g_al);
    cudaGetSymbolAddress((void**)&fh,  g_fh);  cudaGetSymbolAddress((void**)&fl, g_fl);
    cudaGetSymbolAddress((void**)&wqh, g_wqh); cudaGetSymbolAddress((void**)&wql, g_wql);
    cudaGetSymbolAddress((void**)&woh, g_woh); cudaGetSymbolAddress((void**)&wol, g_wol);
    cudaGetSymbolAddress((void**)&w1h, g_w1h); cudaGetSymbolAddress((void**)&w1l, g_w1l);
    cudaGetSymbolAddress((void**)&w2h, g_w2h); cudaGetSymbolAddress((void**)&w2l, g_w2l);

    cudaFuncSetAttribute(attn_kernel, cudaFuncAttributeMaxDynamicSharedMemorySize, ATT_SMEM);
    cudaFuncSetAttribute(tc_gemm<0>, cudaFuncAttributeMaxDynamicSharedMemorySize, GS_TOTAL);
    cudaFuncSetAttribute(tc_gemm<1>, cudaFuncAttributeMaxDynamicSharedMemorySize, GS_TOTAL);
    cudaFuncSetAttribute(tc_gemm<2>, cudaFuncAttributeMaxDynamicSharedMemorySize, GS_TOTAL);

    {
        int n4;
        n4 = NLAYER*3*Dm*Dm/4; split4_kernel<<<(n4+255)/256,256>>>(qkv_w, wqh, wql, n4);
        n4 = NLAYER*Dm*Dm/4;   split4_kernel<<<(n4+255)/256,256>>>(out_w, woh, wol, n4);
        n4 = NLAYER*FFd*Dm/4;  split4_kernel<<<(n4+255)/256,256>>>(ff1_w, w1h, w1l, n4);
        n4 = NLAYER*Dm*FFd/4;  split4_kernel<<<(n4+255)/256,256>>>(ff2_w, w2h, w2l, n4);
    }

    inproj_kernel<<<ROWS, 128>>>(feat, proj_w, proj_b, pe, x, xh, xl);

    for (int l = 0; l < NLAYER; l++) {
        tc_gemm<0><<<dim3(3*Dm/128, ROWS/128), 256, GS_TOTAL>>>(
            xh, xl, wqh + (size_t)l*3*Dm*Dm, wql + (size_t)l*3*Dm*Dm,
            qkv_b + (size_t)l*3*Dm, nullptr, qkv, nullptr, nullptr,
            ROWS, 3*Dm, Dm);
        attn_kernel<<<dim3(Tseq/64, Hh, Bsz), 256, ATT_SMEM>>>(qkv, ah, al);
        tc_gemm<1><<<dim3(Dm/128, ROWS/128), 256, GS_TOTAL>>>(
            ah, al, woh + (size_t)l*Dm*Dm, wol + (size_t)l*Dm*Dm,
            out_b + (size_t)l*Dm, x, y, nullptr, nullptr,
            ROWS, Dm, Dm);
        ln_kernel<<<ROWS, 256>>>(y, ln1_g + (size_t)l*Dm, ln1_b + (size_t)l*Dm, x, xh, xl);
        tc_gemm<2><<<dim3(FFd/128, ROWS/128), 256, GS_TOTAL>>>(
            xh, xl, w1h + (size_t)l*FFd*Dm, w1l + (size_t)l*FFd*Dm,
            ff1_b + (size_t)l*FFd, nullptr, nullptr, fh, fl,
            ROWS, FFd, Dm);
        tc_gemm<1><<<dim3(Dm/128, ROWS/128), 256, GS_TOTAL>>>(
            fh, fl, w2h + (size_t)l*Dm*FFd, w2l + (size_t)l*Dm*FFd,
            ff2_b + (size_t)l*Dm, x, y, nullptr, nullptr,
            ROWS, Dm, FFd);
        if (l == NLAYER - 1)
            ln_kernel<<<ROWS, 256>>>(y, ln2_g + (size_t)l*Dm, ln2_b + (size_t)l*Dm,
                                     (float*)d_out, nullptr, nullptr);
        else
            ln_kernel<<<ROWS, 256>>>(y, ln2_g + (size_t)l*Dm, ln2_b + (size_t)l*Dm, x, xh, xl);
    }
}

// round 5
// speedup vs baseline: 2.2908x; 1.0653x over previous
#include <cuda_runtime.h>
#include <cuda_bf16.h>
#include <cstdint>
#include <cstddef>

#define Bsz 4
#define Tseq 2048
#define Dm 512
#define Hh 8
#define FFd 2048
#define NLAYER 4
#define ROWS (Bsz*Tseq)   /* 8192 */

// ---------------- scratch (device globals; no allocations allowed) ----------
__device__ __align__(128) float g_x  [ROWS*Dm];
__device__ __align__(128) float g_y  [ROWS*Dm];
__device__ __align__(128) __nv_bfloat16 g_qh [ROWS*3*Dm], g_ql[ROWS*3*Dm];
__device__ __align__(128) __nv_bfloat16 g_xh[ROWS*Dm],  g_xl[ROWS*Dm];
__device__ __align__(128) __nv_bfloat16 g_ah[ROWS*Dm],  g_al[ROWS*Dm];
__device__ __align__(128) __nv_bfloat16 g_fh[ROWS*FFd], g_fl[ROWS*FFd];
__device__ __align__(128) __nv_bfloat16 g_wqh[NLAYER*3*Dm*Dm], g_wql[NLAYER*3*Dm*Dm];
__device__ __align__(128) __nv_bfloat16 g_woh[NLAYER*Dm*Dm],   g_wol[NLAYER*Dm*Dm];
__device__ __align__(128) __nv_bfloat16 g_w1h[NLAYER*FFd*Dm],  g_w1l[NLAYER*FFd*Dm];
__device__ __align__(128) __nv_bfloat16 g_w2h[NLAYER*Dm*FFd],  g_w2l[NLAYER*Dm*FFd];

// ---------------- helpers ----------------------------------------------------
__device__ __forceinline__ void cp16(uint32_t s, const void* g) {
    asm volatile("cp.async.cg.shared.global [%0], [%1], 16;" :: "r"(s), "l"(g));
}
__device__ __forceinline__ void cp_commit() {
    asm volatile("cp.async.commit_group;" ::: "memory");
}
template<int N> __device__ __forceinline__ void cp_wait() {
    asm volatile("cp.async.wait_group %0;" :: "n"(N) : "memory");
}
__device__ __forceinline__ void ldsm4(uint32_t* r, uint32_t addr) {
    asm volatile("ldmatrix.sync.aligned.m8n8.x4.shared.b16 {%0,%1,%2,%3}, [%4];"
                 : "=r"(r[0]), "=r"(r[1]), "=r"(r[2]), "=r"(r[3]) : "r"(addr));
}
__device__ __forceinline__ void mma16816(float* c, const uint32_t* a, const uint32_t* b) {
    asm volatile(
        "mma.sync.aligned.m16n8k16.row.col.f32.bf16.bf16.f32 "
        "{%0,%1,%2,%3}, {%4,%5,%6,%7}, {%8,%9}, {%0,%1,%2,%3};"
        : "+f"(c[0]), "+f"(c[1]), "+f"(c[2]), "+f"(c[3])
        : "r"(a[0]), "r"(a[1]), "r"(a[2]), "r"(a[3]), "r"(b[0]), "r"(b[1]));
}

__device__ __forceinline__ void split_store4(__nv_bfloat16* __restrict__ H,
                                             __nv_bfloat16* __restrict__ L,
                                             size_t idx, float4 v) {
    __nv_bfloat16 h0 = __float2bfloat16(v.x), h1 = __float2bfloat16(v.y);
    __nv_bfloat16 h2 = __float2bfloat16(v.z), h3 = __float2bfloat16(v.w);
    __nv_bfloat16 l0 = __float2bfloat16(v.x - __bfloat162float(h0));
    __nv_bfloat16 l1 = __float2bfloat16(v.y - __bfloat162float(h1));
    __nv_bfloat16 l2 = __float2bfloat16(v.z - __bfloat162float(h2));
    __nv_bfloat16 l3 = __float2bfloat16(v.w - __bfloat162float(h3));
    union U { __nv_bfloat16 b[4]; uint2 u; };
    U uh, ul;
    uh.b[0] = h0; uh.b[1] = h1; uh.b[2] = h2; uh.b[3] = h3;
    ul.b[0] = l0; ul.b[1] = l1; ul.b[2] = l2; ul.b[3] = l3;
    *(uint2*)(H + idx) = uh.u;
    *(uint2*)(L + idx) = ul.u;
}
__device__ __forceinline__ void split_store1(__nv_bfloat16* H, __nv_bfloat16* L,
                                             size_t idx, float v) {
    __nv_bfloat16 h = __float2bfloat16(v);
    H[idx] = h;
    L[idx] = __float2bfloat16(v - __bfloat162float(h));
}

// ---------------- weight fp32 -> bf16 hi/lo split ----------------------------
__global__ __launch_bounds__(256)
void split4_kernel(const float* __restrict__ w, __nv_bfloat16* __restrict__ h,
                   __nv_bfloat16* __restrict__ l, int n4) {
    int i = blockIdx.x * 256 + threadIdx.x;
    if (i < n4) {
        float4 v = ((const float4*)w)[i];
        split_store4(h, l, (size_t)i * 4, v);
    }
}

// ---------------- HMMA GEMM: C[M,N] = A[M,K] @ W[N,K]^T ----------------------
// bf16x3 into fp32 acc: C = Ah*Bh + Ah*Bl + Al*Bh.
// MODE 0: Cf = acc + bias
// MODE 1: Cf = acc + bias + res
// MODE 2: Ch/Cl = split(relu(acc + bias))
// MODE 3: Ch/Cl = split(acc + bias)
#define AROW 80
#define TILE_B (128*AROW)
#define STAGE_B (4*TILE_B)
#define NSTAGE 3
#define GS_TOTAL (NSTAGE*STAGE_B)

__device__ __forceinline__ void gload(uint32_t st,
    const __nv_bfloat16* __restrict__ Ah, const __nv_bfloat16* __restrict__ Al,
    const __nv_bfloat16* __restrict__ Bh, const __nv_bfloat16* __restrict__ Bl,
    int bm, int bn, int K, int k0, int tid)
{
    #pragma unroll
    for (int i = 0; i < 2; i++) {
        int idx = tid + i * 256;
        int row = idx >> 2, c = idx & 3;
        uint32_t so = (uint32_t)(row * AROW + c * 16);
        size_t go = (size_t)(bm + row) * K + k0 + c * 8;
        cp16(st + so,          Ah + go);
        cp16(st + TILE_B + so, Al + go);
    }
    #pragma unroll
    for (int i = 0; i < 2; i++) {
        int idx = tid + i * 256;
        int row = idx >> 2, c = idx & 3;
        uint32_t so = (uint32_t)(row * AROW + c * 16);
        size_t go = (size_t)(bn + row) * K + k0 + c * 8;
        cp16(st + 2*TILE_B + so, Bh + go);
        cp16(st + 3*TILE_B + so, Bl + go);
    }
    cp_commit();
}

template<int MODE>
__global__ __launch_bounds__(256, 1)
void tc_gemm(const __nv_bfloat16* __restrict__ Ah, const __nv_bfloat16* __restrict__ Al,
             const __nv_bfloat16* __restrict__ Bh, const __nv_bfloat16* __restrict__ Bl,
             const float* __restrict__ bias, const float* __restrict__ res,
             float* __restrict__ Cf, __nv_bfloat16* __restrict__ Ch,
             __nv_bfloat16* __restrict__ Cl, int M, int N, int K)
{
    extern __shared__ __align__(128) char smem[];
    uint32_t sb = (uint32_t)__cvta_generic_to_shared(smem);
    int tid = threadIdx.x;
    int wid = tid >> 5, lane = tid & 31;
    int bn = blockIdx.x * 128, bm = blockIdx.y * 128;
    int wm = (wid >> 2) * 64;
    int wn = (wid & 3) * 32;

    float acc[4][4][4];
    #pragma unroll
    for (int i = 0; i < 4; i++)
        #pragma unroll
        for (int j = 0; j < 4; j++)
            #pragma unroll
            for (int r = 0; r < 4; r++) acc[i][j][r] = 0.f;

    const int C = K >> 5;
    gload(sb,           Ah, Al, Bh, Bl, bm, bn, K, 0,  tid);
    gload(sb + STAGE_B, Ah, Al, Bh, Bl, bm, bn, K, 32, tid);

    uint32_t a_row = (uint32_t)(lane & 15);
    uint32_t a_koff = (uint32_t)((lane >> 4) * 16);
    uint32_t b_row = (uint32_t)((lane & 7) + ((lane >> 4) << 3));
    uint32_t b_koff = (uint32_t)(((lane >> 3) & 1) * 16);

    for (int c = 0; c < C; c++) {
        if (c + 1 < C) cp_wait<1>(); else cp_wait<0>();
        __syncthreads();
        if (c + 2 < C)
            gload(sb + ((c + 2) % NSTAGE) * STAGE_B, Ah, Al, Bh, Bl, bm, bn, K, (c + 2) * 32, tid);

        uint32_t sa = sb + (c % NSTAGE) * STAGE_B;
        #pragma unroll
        for (int kk = 0; kk < 2; kk++) {
            uint32_t kb = (uint32_t)(kk * 32);
            uint32_t af[2][4][4];
            uint32_t bf[2][2][4];
            #pragma unroll
            for (int mt = 0; mt < 4; mt++) {
                uint32_t ad = sa + (wm + mt*16 + a_row) * AROW + kb + a_koff;
                ldsm4(af[0][mt], ad);
                ldsm4(af[1][mt], ad + TILE_B);
            }
            #pragma unroll
            for (int ng = 0; ng < 2; ng++) {
                uint32_t bd = sa + 2*TILE_B + (wn + ng*16 + b_row) * AROW + kb + b_koff;
                ldsm4(bf[0][ng], bd);
                ldsm4(bf[1][ng], bd + TILE_B);
            }
            #pragma unroll
            for (int mt = 0; mt < 4; mt++)
                #pragma unroll
                for (int ng = 0; ng < 2; ng++)
                    #pragma unroll
                    for (int half = 0; half < 2; half++) {
                        int nt = ng*2 + half;
                        mma16816(acc[mt][nt], af[0][mt], &bf[0][ng][half*2]);
                        mma16816(acc[mt][nt], af[0][mt], &bf[1][ng][half*2]);
                        mma16816(acc[mt][nt], af[1][mt], &bf[0][ng][half*2]);
                    }
        }
    }

    #pragma unroll
    for (int mt = 0; mt < 4; mt++) {
        int m0 = bm + wm + mt*16 + (lane >> 2);
        #pragma unroll
        for (int nt = 0; nt < 4; nt++) {
            int n = bn + wn + nt*8 + (lane & 3)*2;
            float bx = bias[n], by = bias[n+1];
            #pragma unroll
            for (int h = 0; h < 2; h++) {
                int m = m0 + h*8;
                float v0 = acc[mt][nt][h*2]   + bx;
                float v1 = acc[mt][nt][h*2+1] + by;
                size_t idx = (size_t)m * N + n;
                if (MODE == 1) {
                    float2 rv = *(const float2*)&res[idx];
                    v0 += rv.x; v1 += rv.y;
                }
                if (MODE == 2 || MODE == 3) {
                    if (MODE == 2) { v0 = fmaxf(v0, 0.f); v1 = fmaxf(v1, 0.f); }
                    __nv_bfloat16 h0 = __float2bfloat16(v0);
                    __nv_bfloat16 h1 = __float2bfloat16(v1);
                    __nv_bfloat16 l0 = __float2bfloat16(v0 - __bfloat162float(h0));
                    __nv_bfloat16 l1 = __float2bfloat16(v1 - __bfloat162float(h1));
                    union U { __nv_bfloat16 b[2]; uint32_t u; };
                    U uh, ul;
                    uh.b[0] = h0; uh.b[1] = h1;
                    ul.b[0] = l0; ul.b[1] = l1;
                    *(uint32_t*)(Ch + idx) = uh.u;
                    *(uint32_t*)(Cl + idx) = ul.u;
                } else {
                    *(float2*)&Cf[idx] = make_float2(v0, v1);
                }
            }
        }
    }
}

// ---------------- tensor-core banded attention --------------------------------
// Per CTA: (b, h, 64-query tile). K strip = 5 x 64-key blocks [qstart-128, +191].
// S = Q K^T (bf16x3 mma), masked fp32 scores in SMEM, softmax fused with
// P -> bf16 hi/lo (1/sum folded), O = P V (bf16x3 mma, V transposed at fill).
// SMEM byte offsets (bf16 tile pitch 72 elems = 144 B; P pitch 344 elems = 688 B):
#define OFF_QH 0
#define OFF_QL 9216
#define OFF_KH 18432   /* also VT hi in phase C */
#define OFF_KL 27648   /* also VT lo */
#define OFF_S  36864   /* fp32 [64][328] */
#define OFF_PH 120832  /* bf16 [64][344] */
#define OFF_PL 164864
#define ATT_SMEM 208896

__global__ __launch_bounds__(256, 1)
void attn_tc(const __nv_bfloat16* __restrict__ qh, const __nv_bfloat16* __restrict__ ql,
             __nv_bfloat16* __restrict__ outh, __nv_bfloat16* __restrict__ outl)
{
    extern __shared__ __align__(128) char smraw[];
    uint32_t sb = (uint32_t)__cvta_generic_to_shared(smraw);
    float* S = (float*)(smraw + OFF_S);

    int tid = threadIdx.x;
    int wid = tid >> 5, lane = tid & 31;
    int b = blockIdx.z, h = blockIdx.y;
    int qstart = blockIdx.x << 6;
    size_t rowbase = (size_t)b * Tseq;
    int wm = (wid & 1) * 32;        // warp m-offset (queries)
    int wn = (wid >> 1) * 16;       // warp n-offset (keys / dims)

    uint32_t a_row = (uint32_t)(lane & 15);
    uint32_t a_koff = (uint32_t)((lane >> 4) * 16);
    uint32_t b_row = (uint32_t)((lane & 7) + ((lane >> 4) << 3));
    uint32_t b_koff = (uint32_t)(((lane >> 3) & 1) * 16);

    // ---- fill Q tile (64 rows x 64 bf16 hi/lo, pitch 144B) ----
    #pragma unroll
    for (int r = 0; r < 2; r++) {
        int idx = tid + r*256;          // 0..511
        int qi = idx >> 3, seg = idx & 7;
        size_t go = (rowbase + qstart + qi)*1536 + h*64 + seg*8;
        *(uint4*)(smraw + OFF_QH + qi*144 + seg*16) = *(const uint4*)(qh + go);
        *(uint4*)(smraw + OFF_QL + qi*144 + seg*16) = *(const uint4*)(ql + go);
    }
    __syncthreads();

    // ---- hoist Q fragments (2 m-tiles x 4 k-steps, hi+lo) ----
    uint32_t afH[2][4][4], afL[2][4][4];
    #pragma unroll
    for (int mt = 0; mt < 2; mt++)
        #pragma unroll
        for (int ks = 0; ks < 4; ks++) {
            uint32_t ad = sb + OFF_QH + (wm + mt*16 + a_row)*144 + ks*32 + a_koff;
            ldsm4(afH[mt][ks], ad);
            ldsm4(afL[mt][ks], ad + (OFF_QL - OFF_QH));
        }

    const float scale = 0.125f;

    // ---- phase A: S = Q K^T over 5 key blocks ----
    for (int kb = 0; kb < 5; kb++) {
        __syncthreads();
        #pragma unroll
        for (int r = 0; r < 2; r++) {
            int idx = tid + r*256;
            int kj = idx >> 3, seg = idx & 7;
            int ka = qstart - 128 + kb*64 + kj;
            uint4 vH = make_uint4(0,0,0,0), vL = make_uint4(0,0,0,0);
            if (ka >= 0 && ka < Tseq) {
                size_t go = (rowbase + ka)*1536 + 512 + h*64 + seg*8;
                vH = *(const uint4*)(qh + go);
                vL = *(const uint4*)(ql + go);
            }
            *(uint4*)(smraw + OFF_KH + kj*144 + seg*16) = vH;
            *(uint4*)(smraw + OFF_KL + kj*144 + seg*16) = vL;
        }
        __syncthreads();

        float acc[2][2][4];
        #pragma unroll
        for (int i = 0; i < 2; i++)
            #pragma unroll
            for (int j = 0; j < 2; j++)
                #pragma unroll
                for (int r = 0; r < 4; r++) acc[i][j][r] = 0.f;

        #pragma unroll
        for (int ks = 0; ks < 4; ks++) {
            uint32_t bH[4], bL[4];
            uint32_t bd = sb + OFF_KH + (wn + b_row)*144 + ks*32 + b_koff;
            ldsm4(bH, bd);
            ldsm4(bL, bd + (OFF_KL - OFF_KH));
            #pragma unroll
            for (int mt = 0; mt < 2; mt++)
                #pragma unroll
                for (int half = 0; half < 2; half++) {
                    mma16816(acc[mt][half], afH[mt][ks], &bH[half*2]);
                    mma16816(acc[mt][half], afH[mt][ks], &bL[half*2]);
                    mma16816(acc[mt][half], afL[mt][ks], &bH[half*2]);
                }
        }

        // masked store to S
        #pragma unroll
        for (int mt = 0; mt < 2; mt++)
            #pragma unroll
            for (int half = 0; half < 2; half++)
                #pragma unroll
                for (int r = 0; r < 4; r++) {
                    int qi   = wm + mt*16 + (lane >> 2) + (r >> 1)*8;
                    int kidx = kb*64 + wn + half*8 + (lane & 3)*2 + (r & 1);
                    int ka   = qstart - 128 + kidx;
                    int delta = kidx - qi;
                    bool ok = (delta >= 0) && (delta <= 256) && (ka >= 0) && (ka < Tseq);
                    S[qi*328 + kidx] = ok ? acc[mt][half][r] * scale : -1e30f;
                }
    }
    __syncthreads();

    // ---- softmax + P = (e/sum) -> bf16 hi/lo (warp w: queries w*8..w*8+7) ----
    {
        __nv_bfloat16* PH = (__nv_bfloat16*)(smraw + OFF_PH);
        __nv_bfloat16* PL = (__nv_bfloat16*)(smraw + OFF_PL);
        for (int q = wid*8; q < wid*8 + 8; q++) {
            float v[10]; float m = -1e30f;
            #pragma unroll
            for (int i = 0; i < 10; i++) { v[i] = S[q*328 + lane + i*32]; m = fmaxf(m, v[i]); }
            #pragma unroll
            for (int o = 16; o > 0; o >>= 1) m = fmaxf(m, __shfl_xor_sync(0xffffffffu, m, o));
            float ssum = 0.f;
            #pragma unroll
            for (int i = 0; i < 10; i++) { v[i] = __expf(v[i] - m); ssum += v[i]; }
            #pragma unroll
            for (int o = 16; o > 0; o >>= 1) ssum += __shfl_xor_sync(0xffffffffu, ssum, o);
            float rs = 1.0f / ssum;
            #pragma unroll
            for (int i = 0; i < 10; i++) {
                int k = lane + i*32;
                float p = v[i] * rs;
                __nv_bfloat16 ph = __float2bfloat16(p);
                PH[q*344 + k] = ph;
                PL[q*344 + k] = __float2bfloat16(p - __bfloat162float(ph));
            }
        }
    }

    // ---- phase C: O = P V over 5 key blocks (V transposed into SMEM) ----
    float oacc[2][2][4];
    #pragma unroll
    for (int i = 0; i < 2; i++)
        #pragma unroll
        for (int j = 0; j < 2; j++)
            #pragma unroll
            for (int r = 0; r < 4; r++) oacc[i][j][r] = 0.f;

    for (int kb = 0; kb < 5; kb++) {
        __syncthreads();
        #pragma unroll
        for (int r = 0; r < 2; r++) {
            int idx = tid + r*256;
            int kj = idx >> 3, seg = idx & 7;
            int d0 = seg * 8;
            int ka = qstart - 128 + kb*64 + kj;
            union U8 { uint4 u; __nv_bfloat16 bh[8]; } vH, vL;
            vH.u = make_uint4(0,0,0,0); vL.u = make_uint4(0,0,0,0);
            if (ka >= 0 && ka < Tseq) {
                size_t go = (rowbase + ka)*1536 + 1024 + h*64 + d0;
                vH.u = *(const uint4*)(qh + go);
                vL.u = *(const uint4*)(ql + go);
            }
            __nv_bfloat16* VTH = (__nv_bfloat16*)(smraw + OFF_KH);
            __nv_bfloat16* VTL = (__nv_bfloat16*)(smraw + OFF_KL);
            #pragma unroll
            for (int j = 0; j < 8; j++) {
                VTH[(d0 + j)*72 + kj] = vH.bh[j];
                VTL[(d0 + j)*72 + kj] = vL.bh[j];
            }
        }
        __syncthreads();

        #pragma unroll
        for (int ks = 0; ks < 4; ks++) {
            uint32_t aH[2][4], aL[2][4];
            #pragma unroll
            for (int mt = 0; mt < 2; mt++) {
                uint32_t pd = sb + OFF_PH + (wm + mt*16 + a_row)*688 + (kb*64 + ks*16)*2 + a_koff;
                ldsm4(aH[mt], pd);
                ldsm4(aL[mt], pd + (OFF_PL - OFF_PH));
            }
            uint32_t bH[4], bL[4];
            uint32_t bd = sb + OFF_KH + (wn + b_row)*144 + ks*32 + b_koff;
            ldsm4(bH, bd);
            ldsm4(bL, bd + (OFF_KL - OFF_KH));
            #pragma unroll
            for (int mt = 0; mt < 2; mt++)
                #pragma unroll
                for (int half = 0; half < 2; half++) {
                    mma16816(oacc[mt][half], aH[mt], &bH[half*2]);
                    mma16816(oacc[mt][half], aH[mt], &bL[half*2]);
                    mma16816(oacc[mt][half], aL[mt], &bH[half*2]);
                }
        }
    }

    // ---- epilogue: hi/lo split store of O ----
    #pragma unroll
    for (int mt = 0; mt < 2; mt++)
        #pragma unroll
        for (int half = 0; half < 2; half++)
            #pragma unroll
            for (int hr = 0; hr < 2; hr++) {
                int qi = wm + mt*16 + (lane >> 2) + hr*8;
                int d  = wn + half*8 + (lane & 3)*2;
                float v0 = oacc[mt][half][hr*2];
                float v1 = oacc[mt][half][hr*2+1];
                size_t idx = (rowbase + qstart + qi)*512 + h*64 + d;
                __nv_bfloat16 h0 = __float2bfloat16(v0);
                __nv_bfloat16 h1 = __float2bfloat16(v1);
                __nv_bfloat16 l0 = __float2bfloat16(v0 - __bfloat162float(h0));
                __nv_bfloat16 l1 = __float2bfloat16(v1 - __bfloat162float(h1));
                union U { __nv_bfloat16 b[2]; uint32_t u; };
                U uh, ul;
                uh.b[0] = h0; uh.b[1] = h1;
                ul.b[0] = l0; ul.b[1] = l1;
                *(uint32_t*)(outh + idx) = uh.u;
                *(uint32_t*)(outl + idx) = ul.u;
            }
}

// ---------------- LayerNorm (+ optional bf16 hi/lo output) ------------------
__global__ __launch_bounds__(256)
void ln_kernel(const float* __restrict__ in, const float* __restrict__ gam,
               const float* __restrict__ bet, float* __restrict__ out,
               __nv_bfloat16* __restrict__ oh, __nv_bfloat16* __restrict__ ol)
{
    int row = blockIdx.x, tid = threadIdx.x;
    const float* p = in + (size_t)row * 512;
    float x0 = p[tid], x1 = p[tid + 256];
    float s = x0 + x1, q = x0*x0 + x1*x1;
    #pragma unroll
    for (int o = 16; o > 0; o >>= 1) {
        s += __shfl_xor_sync(0xffffffffu, s, o);
        q += __shfl_xor_sync(0xffffffffu, q, o);
    }
    __shared__ float ss[8], sq[8];
    int w = tid >> 5, l = tid & 31;
    if (l == 0) { ss[w] = s; sq[w] = q; }
    __syncthreads();
    float ts = 0.f, tq = 0.f;
    #pragma unroll
    for (int i = 0; i < 8; i++) { ts += ss[i]; tq += sq[i]; }
    float mean = ts * (1.0f/512.0f);
    float var  = tq * (1.0f/512.0f) - mean*mean;
    float inv  = rsqrtf(var + 1e-5f);
    float v0 = (x0 - mean) * inv * gam[tid]       + bet[tid];
    float v1 = (x1 - mean) * inv * gam[tid + 256] + bet[tid + 256];
    float* o = out + (size_t)row * 512;
    o[tid]       = v0;
    o[tid + 256] = v1;
    if (oh) {
        split_store1(oh, ol, (size_t)row*512 + tid,       v0);
        split_store1(oh, ol, (size_t)row*512 + tid + 256, v1);
    }
}

// ---------------- input projection ------------------------------------------
__global__ __launch_bounds__(128)
void inproj_kernel(const float* __restrict__ feat, const float* __restrict__ w,
                   const float* __restrict__ bias, const float* __restrict__ pe,
                   float* __restrict__ out, __nv_bfloat16* __restrict__ oh,
                   __nv_bfloat16* __restrict__ ol)
{
    int row = blockIdx.x;
    int t = row & (Tseq - 1);
    __shared__ float f[32];
    if (threadIdx.x < 32) f[threadIdx.x] = feat[(size_t)row*32 + threadIdx.x];
    __syncthreads();
    int d0 = threadIdx.x * 4;
    float a[4];
    #pragma unroll
    for (int j = 0; j < 4; j++) a[j] = bias[d0 + j];
    #pragma unroll
    for (int j = 0; j < 4; j++) {
        const float4* wp = (const float4*)(w + (size_t)(d0 + j) * 32);
        #pragma unroll
        for (int k4 = 0; k4 < 8; k4++) {
            float4 wv = wp[k4];
            a[j] += wv.x*f[k4*4] + wv.y*f[k4*4+1] + wv.z*f[k4*4+2] + wv.w*f[k4*4+3];
        }
    }
    float4 pev = *(const float4*)(pe + (size_t)t*512 + d0);
    float4 r = make_float4(a[0]+pev.x, a[1]+pev.y, a[2]+pev.z, a[3]+pev.w);
    *(float4*)(out + (size_t)row*512 + d0) = r;
    split_store4(oh, ol, (size_t)row*512 + d0, r);
}

// ---------------- launch ----------------------------------------------------
extern "C" void kernel_launch(void* const* d_in, const int* in_sizes, int n_in,
                              void* d_out, int out_size)
{
    const float* feat   = (const float*)d_in[0];
    const float* proj_w = (const float*)d_in[2];
    const float* proj_b = (const float*)d_in[3];
    const float* pe     = (const float*)d_in[4];
    const float* qkv_w  = (const float*)d_in[5];
    const float* qkv_b  = (const float*)d_in[6];
    const float* out_w  = (const float*)d_in[7];
    const float* out_b  = (const float*)d_in[8];
    const float* ff1_w  = (const float*)d_in[9];
    const float* ff1_b  = (const float*)d_in[10];
    const float* ff2_w  = (const float*)d_in[11];
    const float* ff2_b  = (const float*)d_in[12];
    const float* ln1_g  = (const float*)d_in[13];
    const float* ln1_b  = (const float*)d_in[14];
    const float* ln2_g  = (const float*)d_in[15];
    const float* ln2_b  = (const float*)d_in[16];

    float *x, *y;
    __nv_bfloat16 *qh, *ql, *xh, *xl, *ah, *al, *fh, *fl;
    __nv_bfloat16 *wqh, *wql, *woh, *wol, *w1h, *w1l, *w2h, *w2l;
    cudaGetSymbolAddress((void**)&x,   g_x);
    cudaGetSymbolAddress((void**)&y,   g_y);
    cudaGetSymbolAddress((void**)&qh,  g_qh);  cudaGetSymbolAddress((void**)&ql, g_ql);
    cudaGetSymbolAddress((void**)&xh,  g_xh);  cudaGetSymbolAddress((void**)&xl, g_xl);
    cudaGetSymbolAddress((void**)&ah,  g_ah);  cudaGetSymbolAddress((void**)&al, g_al);
    cudaGetSymbolAddress((void**)&fh,  g_fh);  cudaGetSymbolAddress((void**)&fl, g_fl);
    cudaGetSymbolAddress((void**)&wqh, g_wqh); cudaGetSymbolAddress((void**)&wql, g_wql);
    cudaGetSymbolAddress((void**)&woh, g_woh); cudaGetSymbolAddress((void**)&wol, g_wol);
    cudaGetSymbolAddress((void**)&w1h, g_w1h); cudaGetSymbolAddress((void**)&w1l, g_w1l);
    cudaGetSymbolAddress((void**)&w2h, g_w2h); cudaGetSymbolAddress((void**)&w2l, g_w2l);

    cudaFuncSetAttribute(attn_tc,    cudaFuncAttributeMaxDynamicSharedMemorySize, ATT_SMEM);
    cudaFuncSetAttribute(tc_gemm<0>, cudaFuncAttributeMaxDynamicSharedMemorySize, GS_TOTAL);
    cudaFuncSetAttribute(tc_gemm<1>, cudaFuncAttributeMaxDynamicSharedMemorySize, GS_TOTAL);
    cudaFuncSetAttribute(tc_gemm<2>, cudaFuncAttributeMaxDynamicSharedMemorySize, GS_TOTAL);
    cudaFuncSetAttribute(tc_gemm<3>, cudaFuncAttributeMaxDynamicSharedMemorySize, GS_TOTAL);

    {
        int n4;
        n4 = NLAYER*3*Dm*Dm/4; split4_kernel<<<(n4+255)/256,256>>>(qkv_w, wqh, wql, n4);
        n4 = NLAYER*Dm*Dm/4;   split4_kernel<<<(n4+255)/256,256>>>(out_w, woh, wol, n4);
        n4 = NLAYER*FFd*Dm/4;  split4_kernel<<<(n4+255)/256,256>>>(ff1_w, w1h, w1l, n4);
        n4 = NLAYER*Dm*FFd/4;  split4_kernel<<<(n4+255)/256,256>>>(ff2_w, w2h, w2l, n4);
    }

    inproj_kernel<<<ROWS, 128>>>(feat, proj_w, proj_b, pe, x, xh, xl);

    for (int l = 0; l < NLAYER; l++) {
        // QKV -> bf16 hi/lo directly
        tc_gemm<3><<<dim3(3*Dm/128, ROWS/128), 256, GS_TOTAL>>>(
            xh, xl, wqh + (size_t)l*3*Dm*Dm, wql + (size_t)l*3*Dm*Dm,
            qkv_b + (size_t)l*3*Dm, nullptr, nullptr, qh, ql,
            ROWS, 3*Dm, Dm);
        // tensor-core banded attention -> (ah, al)
        attn_tc<<<dim3(Tseq/64, Hh, Bsz), 256, ATT_SMEM>>>(qh, ql, ah, al);
        // out proj + residual(x) -> y
        tc_gemm<1><<<dim3(Dm/128, ROWS/128), 256, GS_TOTAL>>>(
            ah, al, woh + (size_t)l*Dm*Dm, wol + (size_t)l*Dm*Dm,
            out_b + (size_t)l*Dm, x, y, nullptr, nullptr,
            ROWS, Dm, Dm);
        ln_kernel<<<ROWS, 256>>>(y, ln1_g + (size_t)l*Dm, ln1_b + (size_t)l*Dm, x, xh, xl);
        tc_gemm<2><<<dim3(FFd/128, ROWS/128), 256, GS_TOTAL>>>(
            xh, xl, w1h + (size_t)l*FFd*Dm, w1l + (size_t)l*FFd*Dm,
            ff1_b + (size_t)l*FFd, nullptr, nullptr, fh, fl,
            ROWS, FFd, Dm);
        tc_gemm<1><<<dim3(Dm/128, ROWS/128), 256, GS_TOTAL>>>(
            fh, fl, w2h + (size_t)l*Dm*FFd, w2l + (size_t)l*Dm*FFd,
            ff2_b + (size_t)l*Dm, x, y, nullptr, nullptr,
            ROWS, Dm, FFd);
        if (l == NLAYER - 1)
            ln_kernel<<<ROWS, 256>>>(y, ln2_g + (size_t)l*Dm, ln2_b + (size_t)l*Dm,
                                     (float*)d_out, nullptr, nullptr);
        else
            ln_kernel<<<ROWS, 256>>>(y, ln2_g + (size_t)l*Dm, ln2_b + (size_t)l*Dm, x, xh, xl);
    }
}

// round 6
// speedup vs baseline: 2.3949x; 1.0455x over previous
#include <cuda_runtime.h>
#include <cuda_bf16.h>
#include <cstdint>
#include <cstddef>

#define Bsz 4
#define Tseq 2048
#define Dm 512
#define Hh 8
#define FFd 2048
#define NLAYER 4
#define ROWS (Bsz*Tseq)   /* 8192 */

// ---------------- scratch (device globals; no allocations allowed) ----------
__device__ __align__(128) float g_x  [ROWS*Dm];
__device__ __align__(128) float g_y  [ROWS*Dm];
__device__ __align__(128) __nv_bfloat16 g_qh [ROWS*3*Dm], g_ql[ROWS*3*Dm];
__device__ __align__(128) __nv_bfloat16 g_xh[ROWS*Dm],  g_xl[ROWS*Dm];
__device__ __align__(128) __nv_bfloat16 g_ah[ROWS*Dm],  g_al[ROWS*Dm];
__device__ __align__(128) __nv_bfloat16 g_fh[ROWS*FFd], g_fl[ROWS*FFd];
__device__ __align__(128) __nv_bfloat16 g_wqh[NLAYER*3*Dm*Dm], g_wql[NLAYER*3*Dm*Dm];
__device__ __align__(128) __nv_bfloat16 g_woh[NLAYER*Dm*Dm],   g_wol[NLAYER*Dm*Dm];
__device__ __align__(128) __nv_bfloat16 g_w1h[NLAYER*FFd*Dm],  g_w1l[NLAYER*FFd*Dm];
__device__ __align__(128) __nv_bfloat16 g_w2h[NLAYER*Dm*FFd],  g_w2l[NLAYER*Dm*FFd];

// ---------------- helpers ----------------------------------------------------
__device__ __forceinline__ void cp16(uint32_t s, const void* g) {
    asm volatile("cp.async.cg.shared.global [%0], [%1], 16;" :: "r"(s), "l"(g));
}
__device__ __forceinline__ void cp_commit() {
    asm volatile("cp.async.commit_group;" ::: "memory");
}
template<int N> __device__ __forceinline__ void cp_wait() {
    asm volatile("cp.async.wait_group %0;" :: "n"(N) : "memory");
}
__device__ __forceinline__ void ldsm4(uint32_t* r, uint32_t addr) {
    asm volatile("ldmatrix.sync.aligned.m8n8.x4.shared.b16 {%0,%1,%2,%3}, [%4];"
                 : "=r"(r[0]), "=r"(r[1]), "=r"(r[2]), "=r"(r[3]) : "r"(addr));
}
__device__ __forceinline__ void mma16816(float* c, const uint32_t* a, const uint32_t* b) {
    asm volatile(
        "mma.sync.aligned.m16n8k16.row.col.f32.bf16.bf16.f32 "
        "{%0,%1,%2,%3}, {%4,%5,%6,%7}, {%8,%9}, {%0,%1,%2,%3};"
        : "+f"(c[0]), "+f"(c[1]), "+f"(c[2]), "+f"(c[3])
        : "r"(a[0]), "r"(a[1]), "r"(a[2]), "r"(a[3]), "r"(b[0]), "r"(b[1]));
}

__device__ __forceinline__ void split_store4(__nv_bfloat16* __restrict__ H,
                                             __nv_bfloat16* __restrict__ L,
                                             size_t idx, float4 v) {
    __nv_bfloat16 h0 = __float2bfloat16(v.x), h1 = __float2bfloat16(v.y);
    __nv_bfloat16 h2 = __float2bfloat16(v.z), h3 = __float2bfloat16(v.w);
    __nv_bfloat16 l0 = __float2bfloat16(v.x - __bfloat162float(h0));
    __nv_bfloat16 l1 = __float2bfloat16(v.y - __bfloat162float(h1));
    __nv_bfloat16 l2 = __float2bfloat16(v.z - __bfloat162float(h2));
    __nv_bfloat16 l3 = __float2bfloat16(v.w - __bfloat162float(h3));
    union U { __nv_bfloat16 b[4]; uint2 u; };
    U uh, ul;
    uh.b[0] = h0; uh.b[1] = h1; uh.b[2] = h2; uh.b[3] = h3;
    ul.b[0] = l0; ul.b[1] = l1; ul.b[2] = l2; ul.b[3] = l3;
    *(uint2*)(H + idx) = uh.u;
    *(uint2*)(L + idx) = ul.u;
}
__device__ __forceinline__ void split_store1(__nv_bfloat16* H, __nv_bfloat16* L,
                                             size_t idx, float v) {
    __nv_bfloat16 h = __float2bfloat16(v);
    H[idx] = h;
    L[idx] = __float2bfloat16(v - __bfloat162float(h));
}

// ---------------- weight fp32 -> bf16 hi/lo split ----------------------------
__global__ __launch_bounds__(256)
void split4_kernel(const float* __restrict__ w, __nv_bfloat16* __restrict__ h,
                   __nv_bfloat16* __restrict__ l, int n4) {
    int i = blockIdx.x * 256 + threadIdx.x;
    if (i < n4) {
        float4 v = ((const float4*)w)[i];
        split_store4(h, l, (size_t)i * 4, v);
    }
}

// ---------------- HMMA GEMM: C[M,N] = A[M,K] @ W[N,K]^T ----------------------
// bf16x3 into fp32 acc: C = Ah*Bh + Ah*Bl + Al*Bh.
// BM=128, BN=256, BK=32, 256 threads (8 warps, warp tile 64x64), 3-stage cp.async.
// MODE 0: Cf = acc + bias
// MODE 1: Cf = acc + bias + res
// MODE 2: Ch/Cl = split(relu(acc + bias))
// MODE 3: Ch/Cl = split(acc + bias)
#define AROW 80
#define A_TILE (128*AROW)            /* 10240 */
#define B_TILE (256*AROW)            /* 20480 */
#define STAGE_B (2*A_TILE + 2*B_TILE) /* 61440 */
#define NSTAGE 3
#define GS_TOTAL (NSTAGE*STAGE_B)    /* 184320 */

__device__ __forceinline__ void gload(uint32_t st,
    const __nv_bfloat16* __restrict__ Ah, const __nv_bfloat16* __restrict__ Al,
    const __nv_bfloat16* __restrict__ Bh, const __nv_bfloat16* __restrict__ Bl,
    int bm, int bn, int K, int k0, int tid)
{
    #pragma unroll
    for (int i = 0; i < 2; i++) {                 // A: 128 rows x 64B x (hi,lo)
        int idx = tid + i * 256;                  // 0..511
        int row = idx >> 2, c = idx & 3;
        uint32_t so = (uint32_t)(row * AROW + c * 16);
        size_t go = (size_t)(bm + row) * K + k0 + c * 8;
        cp16(st + so,          Ah + go);
        cp16(st + A_TILE + so, Al + go);
    }
    #pragma unroll
    for (int i = 0; i < 4; i++) {                 // B: 256 rows x 64B x (hi,lo)
        int idx = tid + i * 256;                  // 0..1023
        int row = idx >> 2, c = idx & 3;
        uint32_t so = (uint32_t)(row * AROW + c * 16);
        size_t go = (size_t)(bn + row) * K + k0 + c * 8;
        cp16(st + 2*A_TILE + so,          Bh + go);
        cp16(st + 2*A_TILE + B_TILE + so, Bl + go);
    }
    cp_commit();
}

template<int MODE>
__global__ __launch_bounds__(256, 1)
void tc_gemm(const __nv_bfloat16* __restrict__ Ah, const __nv_bfloat16* __restrict__ Al,
             const __nv_bfloat16* __restrict__ Bh, const __nv_bfloat16* __restrict__ Bl,
             const float* __restrict__ bias, const float* __restrict__ res,
             float* __restrict__ Cf, __nv_bfloat16* __restrict__ Ch,
             __nv_bfloat16* __restrict__ Cl, int M, int N, int K)
{
    extern __shared__ __align__(128) char smem[];
    uint32_t sb = (uint32_t)__cvta_generic_to_shared(smem);
    int tid = threadIdx.x;
    int wid = tid >> 5, lane = tid & 31;
    int bn = blockIdx.x * 256, bm = blockIdx.y * 128;
    int wm = (wid & 1) * 64;      // warp m-offset (0/64)
    int wn = (wid >> 1) * 64;     // warp n-offset (0/64/128/192)

    float acc[4][8][4];
    #pragma unroll
    for (int i = 0; i < 4; i++)
        #pragma unroll
        for (int j = 0; j < 8; j++)
            #pragma unroll
            for (int r = 0; r < 4; r++) acc[i][j][r] = 0.f;

    const int C = K >> 5;
    gload(sb,           Ah, Al, Bh, Bl, bm, bn, K, 0,  tid);
    gload(sb + STAGE_B, Ah, Al, Bh, Bl, bm, bn, K, 32, tid);

    uint32_t a_row = (uint32_t)(lane & 15);
    uint32_t a_koff = (uint32_t)((lane >> 4) * 16);
    uint32_t b_row = (uint32_t)((lane & 7) + ((lane >> 4) << 3));
    uint32_t b_koff = (uint32_t)(((lane >> 3) & 1) * 16);

    for (int c = 0; c < C; c++) {
        if (c + 1 < C) cp_wait<1>(); else cp_wait<0>();
        __syncthreads();
        if (c + 2 < C)
            gload(sb + ((c + 2) % NSTAGE) * STAGE_B, Ah, Al, Bh, Bl, bm, bn, K, (c + 2) * 32, tid);

        uint32_t sa = sb + (c % NSTAGE) * STAGE_B;
        #pragma unroll
        for (int kk = 0; kk < 2; kk++) {
            uint32_t kb = (uint32_t)(kk * 32);
            uint32_t afH[4][4], afL[4][4];
            #pragma unroll
            for (int mt = 0; mt < 4; mt++) {
                uint32_t ad = sa + (wm + mt*16 + a_row) * AROW + kb + a_koff;
                ldsm4(afH[mt], ad);
                ldsm4(afL[mt], ad + A_TILE);
            }
            #pragma unroll
            for (int ng = 0; ng < 4; ng++) {
                uint32_t bH[4], bL[4];
                uint32_t bd = sa + 2*A_TILE + (wn + ng*16 + b_row) * AROW + kb + b_koff;
                ldsm4(bH, bd);
                ldsm4(bL, bd + B_TILE);
                #pragma unroll
                for (int mt = 0; mt < 4; mt++)
                    #pragma unroll
                    for (int half = 0; half < 2; half++) {
                        int nt = ng*2 + half;
                        mma16816(acc[mt][nt], afH[mt], &bH[half*2]);
                        mma16816(acc[mt][nt], afH[mt], &bL[half*2]);
                        mma16816(acc[mt][nt], afL[mt], &bH[half*2]);
                    }
            }
        }
    }

    #pragma unroll
    for (int mt = 0; mt < 4; mt++) {
        int m0 = bm + wm + mt*16 + (lane >> 2);
        #pragma unroll
        for (int nt = 0; nt < 8; nt++) {
            int n = bn + wn + nt*8 + (lane & 3)*2;
            float bx = bias[n], by = bias[n+1];
            #pragma unroll
            for (int h = 0; h < 2; h++) {
                int m = m0 + h*8;
                float v0 = acc[mt][nt][h*2]   + bx;
                float v1 = acc[mt][nt][h*2+1] + by;
                size_t idx = (size_t)m * N + n;
                if (MODE == 1) {
                    float2 rv = *(const float2*)&res[idx];
                    v0 += rv.x; v1 += rv.y;
                }
                if (MODE == 2 || MODE == 3) {
                    if (MODE == 2) { v0 = fmaxf(v0, 0.f); v1 = fmaxf(v1, 0.f); }
                    __nv_bfloat16 h0 = __float2bfloat16(v0);
                    __nv_bfloat16 h1 = __float2bfloat16(v1);
                    __nv_bfloat16 l0 = __float2bfloat16(v0 - __bfloat162float(h0));
                    __nv_bfloat16 l1 = __float2bfloat16(v1 - __bfloat162float(h1));
                    union U { __nv_bfloat16 b[2]; uint32_t u; };
                    U uh, ul;
                    uh.b[0] = h0; uh.b[1] = h1;
                    ul.b[0] = l0; ul.b[1] = l1;
                    *(uint32_t*)(Ch + idx) = uh.u;
                    *(uint32_t*)(Cl + idx) = ul.u;
                } else {
                    *(float2*)&Cf[idx] = make_float2(v0, v1);
                }
            }
        }
    }
}

// ---------------- tensor-core banded attention --------------------------------
#define OFF_QH 0
#define OFF_QL 9216
#define OFF_KH 18432   /* also VT hi in phase C */
#define OFF_KL 27648   /* also VT lo */
#define OFF_S  36864   /* fp32 [64][328] */
#define OFF_PH 120832  /* bf16 [64][344] */
#define OFF_PL 164864
#define ATT_SMEM 208896

__global__ __launch_bounds__(256, 1)
void attn_tc(const __nv_bfloat16* __restrict__ qh, const __nv_bfloat16* __restrict__ ql,
             __nv_bfloat16* __restrict__ outh, __nv_bfloat16* __restrict__ outl)
{
    extern __shared__ __align__(128) char smraw[];
    uint32_t sb = (uint32_t)__cvta_generic_to_shared(smraw);
    float* S = (float*)(smraw + OFF_S);

    int tid = threadIdx.x;
    int wid = tid >> 5, lane = tid & 31;
    int b = blockIdx.z, h = blockIdx.y;
    int qstart = blockIdx.x << 6;
    size_t rowbase = (size_t)b * Tseq;
    int wm = (wid & 1) * 32;
    int wn = (wid >> 1) * 16;

    uint32_t a_row = (uint32_t)(lane & 15);
    uint32_t a_koff = (uint32_t)((lane >> 4) * 16);
    uint32_t b_row = (uint32_t)((lane & 7) + ((lane >> 4) << 3));
    uint32_t b_koff = (uint32_t)(((lane >> 3) & 1) * 16);

    #pragma unroll
    for (int r = 0; r < 2; r++) {
        int idx = tid + r*256;
        int qi = idx >> 3, seg = idx & 7;
        size_t go = (rowbase + qstart + qi)*1536 + h*64 + seg*8;
        *(uint4*)(smraw + OFF_QH + qi*144 + seg*16) = *(const uint4*)(qh + go);
        *(uint4*)(smraw + OFF_QL + qi*144 + seg*16) = *(const uint4*)(ql + go);
    }
    __syncthreads();

    uint32_t afH[2][4][4], afL[2][4][4];
    #pragma unroll
    for (int mt = 0; mt < 2; mt++)
        #pragma unroll
        for (int ks = 0; ks < 4; ks++) {
            uint32_t ad = sb + OFF_QH + (wm + mt*16 + a_row)*144 + ks*32 + a_koff;
            ldsm4(afH[mt][ks], ad);
            ldsm4(afL[mt][ks], ad + (OFF_QL - OFF_QH));
        }

    const float scale = 0.125f;

    for (int kb = 0; kb < 5; kb++) {
        __syncthreads();
        #pragma unroll
        for (int r = 0; r < 2; r++) {
            int idx = tid + r*256;
            int kj = idx >> 3, seg = idx & 7;
            int ka = qstart - 128 + kb*64 + kj;
            uint4 vH = make_uint4(0,0,0,0), vL = make_uint4(0,0,0,0);
            if (ka >= 0 && ka < Tseq) {
                size_t go = (rowbase + ka)*1536 + 512 + h*64 + seg*8;
                vH = *(const uint4*)(qh + go);
                vL = *(const uint4*)(ql + go);
            }
            *(uint4*)(smraw + OFF_KH + kj*144 + seg*16) = vH;
            *(uint4*)(smraw + OFF_KL + kj*144 + seg*16) = vL;
        }
        __syncthreads();

        float acc[2][2][4];
        #pragma unroll
        for (int i = 0; i < 2; i++)
            #pragma unroll
            for (int j = 0; j < 2; j++)
                #pragma unroll
                for (int r = 0; r < 4; r++) acc[i][j][r] = 0.f;

        #pragma unroll
        for (int ks = 0; ks < 4; ks++) {
            uint32_t bH[4], bL[4];
            uint32_t bd = sb + OFF_KH + (wn + b_row)*144 + ks*32 + b_koff;
            ldsm4(bH, bd);
            ldsm4(bL, bd + (OFF_KL - OFF_KH));
            #pragma unroll
            for (int mt = 0; mt < 2; mt++)
                #pragma unroll
                for (int half = 0; half < 2; half++) {
                    mma16816(acc[mt][half], afH[mt][ks], &bH[half*2]);
                    mma16816(acc[mt][half], afH[mt][ks], &bL[half*2]);
                    mma16816(acc[mt][half], afL[mt][ks], &bH[half*2]);
                }
        }

        #pragma unroll
        for (int mt = 0; mt < 2; mt++)
            #pragma unroll
            for (int half = 0; half < 2; half++)
                #pragma unroll
                for (int r = 0; r < 4; r++) {
                    int qi   = wm + mt*16 + (lane >> 2) + (r >> 1)*8;
                    int kidx = kb*64 + wn + half*8 + (lane & 3)*2 + (r & 1);
                    int ka   = qstart - 128 + kidx;
                    int delta = kidx - qi;
                    bool ok = (delta >= 0) && (delta <= 256) && (ka >= 0) && (ka < Tseq);
                    S[qi*328 + kidx] = ok ? acc[mt][half][r] * scale : -1e30f;
                }
    }
    __syncthreads();

    {
        __nv_bfloat16* PH = (__nv_bfloat16*)(smraw + OFF_PH);
        __nv_bfloat16* PL = (__nv_bfloat16*)(smraw + OFF_PL);
        for (int q = wid*8; q < wid*8 + 8; q++) {
            float v[10]; float m = -1e30f;
            #pragma unroll
            for (int i = 0; i < 10; i++) { v[i] = S[q*328 + lane + i*32]; m = fmaxf(m, v[i]); }
            #pragma unroll
            for (int o = 16; o > 0; o >>= 1) m = fmaxf(m, __shfl_xor_sync(0xffffffffu, m, o));
            float ssum = 0.f;
            #pragma unroll
            for (int i = 0; i < 10; i++) { v[i] = __expf(v[i] - m); ssum += v[i]; }
            #pragma unroll
            for (int o = 16; o > 0; o >>= 1) ssum += __shfl_xor_sync(0xffffffffu, ssum, o);
            float rs = 1.0f / ssum;
            #pragma unroll
            for (int i = 0; i < 10; i++) {
                int k = lane + i*32;
                float p = v[i] * rs;
                __nv_bfloat16 ph = __float2bfloat16(p);
                PH[q*344 + k] = ph;
                PL[q*344 + k] = __float2bfloat16(p - __bfloat162float(ph));
            }
        }
    }

    float oacc[2][2][4];
    #pragma unroll
    for (int i = 0; i < 2; i++)
        #pragma unroll
        for (int j = 0; j < 2; j++)
            #pragma unroll
            for (int r = 0; r < 4; r++) oacc[i][j][r] = 0.f;

    for (int kb = 0; kb < 5; kb++) {
        __syncthreads();
        #pragma unroll
        for (int r = 0; r < 2; r++) {
            int idx = tid + r*256;
            int kj = idx >> 3, seg = idx & 7;
            int d0 = seg * 8;
            int ka = qstart - 128 + kb*64 + kj;
            union U8 { uint4 u; __nv_bfloat16 bh[8]; } vH, vL;
            vH.u = make_uint4(0,0,0,0); vL.u = make_uint4(0,0,0,0);
            if (ka >= 0 && ka < Tseq) {
                size_t go = (rowbase + ka)*1536 + 1024 + h*64 + d0;
                vH.u = *(const uint4*)(qh + go);
                vL.u = *(const uint4*)(ql + go);
            }
            __nv_bfloat16* VTH = (__nv_bfloat16*)(smraw + OFF_KH);
            __nv_bfloat16* VTL = (__nv_bfloat16*)(smraw + OFF_KL);
            #pragma unroll
            for (int j = 0; j < 8; j++) {
                VTH[(d0 + j)*72 + kj] = vH.bh[j];
                VTL[(d0 + j)*72 + kj] = vL.bh[j];
            }
        }
        __syncthreads();

        #pragma unroll
        for (int ks = 0; ks < 4; ks++) {
            uint32_t aH[2][4], aL[2][4];
            #pragma unroll
            for (int mt = 0; mt < 2; mt++) {
                uint32_t pd = sb + OFF_PH + (wm + mt*16 + a_row)*688 + (kb*64 + ks*16)*2 + a_koff;
                ldsm4(aH[mt], pd);
                ldsm4(aL[mt], pd + (OFF_PL - OFF_PH));
            }
            uint32_t bH[4], bL[4];
            uint32_t bd = sb + OFF_KH + (wn + b_row)*144 + ks*32 + b_koff;
            ldsm4(bH, bd);
            ldsm4(bL, bd + (OFF_KL - OFF_KH));
            #pragma unroll
            for (int mt = 0; mt < 2; mt++)
                #pragma unroll
                for (int half = 0; half < 2; half++) {
                    mma16816(oacc[mt][half], aH[mt], &bH[half*2]);
                    mma16816(oacc[mt][half], aH[mt], &bL[half*2]);
                    mma16816(oacc[mt][half], aL[mt], &bH[half*2]);
                }
        }
    }

    #pragma unroll
    for (int mt = 0; mt < 2; mt++)
        #pragma unroll
        for (int half = 0; half < 2; half++)
            #pragma unroll
            for (int hr = 0; hr < 2; hr++) {
                int qi = wm + mt*16 + (lane >> 2) + hr*8;
                int d  = wn + half*8 + (lane & 3)*2;
                float v0 = oacc[mt][half][hr*2];
                float v1 = oacc[mt][half][hr*2+1];
                size_t idx = (rowbase + qstart + qi)*512 + h*64 + d;
                __nv_bfloat16 h0 = __float2bfloat16(v0);
                __nv_bfloat16 h1 = __float2bfloat16(v1);
                __nv_bfloat16 l0 = __float2bfloat16(v0 - __bfloat162float(h0));
                __nv_bfloat16 l1 = __float2bfloat16(v1 - __bfloat162float(h1));
                union U { __nv_bfloat16 b[2]; uint32_t u; };
                U uh, ul;
                uh.b[0] = h0; uh.b[1] = h1;
                ul.b[0] = l0; ul.b[1] = l1;
                *(uint32_t*)(outh + idx) = uh.u;
                *(uint32_t*)(outl + idx) = ul.u;
            }
}

// ---------------- LayerNorm (+ optional bf16 hi/lo output) ------------------
__global__ __launch_bounds__(256)
void ln_kernel(const float* __restrict__ in, const float* __restrict__ gam,
               const float* __restrict__ bet, float* __restrict__ out,
               __nv_bfloat16* __restrict__ oh, __nv_bfloat16* __restrict__ ol)
{
    int row = blockIdx.x, tid = threadIdx.x;
    const float* p = in + (size_t)row * 512;
    float x0 = p[tid], x1 = p[tid + 256];
    float s = x0 + x1, q = x0*x0 + x1*x1;
    #pragma unroll
    for (int o = 16; o > 0; o >>= 1) {
        s += __shfl_xor_sync(0xffffffffu, s, o);
        q += __shfl_xor_sync(0xffffffffu, q, o);
    }
    __shared__ float ss[8], sq[8];
    int w = tid >> 5, l = tid & 31;
    if (l == 0) { ss[w] = s; sq[w] = q; }
    __syncthreads();
    float ts = 0.f, tq = 0.f;
    #pragma unroll
    for (int i = 0; i < 8; i++) { ts += ss[i]; tq += sq[i]; }
    float mean = ts * (1.0f/512.0f);
    float var  = tq * (1.0f/512.0f) - mean*mean;
    float inv  = rsqrtf(var + 1e-5f);
    float v0 = (x0 - mean) * inv * gam[tid]       + bet[tid];
    float v1 = (x1 - mean) * inv * gam[tid + 256] + bet[tid + 256];
    float* o = out + (size_t)row * 512;
    o[tid]       = v0;
    o[tid + 256] = v1;
    if (oh) {
        split_store1(oh, ol, (size_t)row*512 + tid,       v0);
        split_store1(oh, ol, (size_t)row*512 + tid + 256, v1);
    }
}

// ---------------- input projection ------------------------------------------
__global__ __launch_bounds__(128)
void inproj_kernel(const float* __restrict__ feat, const float* __restrict__ w,
                   const float* __restrict__ bias, const float* __restrict__ pe,
                   float* __restrict__ out, __nv_bfloat16* __restrict__ oh,
                   __nv_bfloat16* __restrict__ ol)
{
    int row = blockIdx.x;
    int t = row & (Tseq - 1);
    __shared__ float f[32];
    if (threadIdx.x < 32) f[threadIdx.x] = feat[(size_t)row*32 + threadIdx.x];
    __syncthreads();
    int d0 = threadIdx.x * 4;
    float a[4];
    #pragma unroll
    for (int j = 0; j < 4; j++) a[j] = bias[d0 + j];
    #pragma unroll
    for (int j = 0; j < 4; j++) {
        const float4* wp = (const float4*)(w + (size_t)(d0 + j) * 32);
        #pragma unroll
        for (int k4 = 0; k4 < 8; k4++) {
            float4 wv = wp[k4];
            a[j] += wv.x*f[k4*4] + wv.y*f[k4*4+1] + wv.z*f[k4*4+2] + wv.w*f[k4*4+3];
        }
    }
    float4 pev = *(const float4*)(pe + (size_t)t*512 + d0);
    float4 r = make_float4(a[0]+pev.x, a[1]+pev.y, a[2]+pev.z, a[3]+pev.w);
    *(float4*)(out + (size_t)row*512 + d0) = r;
    split_store4(oh, ol, (size_t)row*512 + d0, r);
}

// ---------------- launch ----------------------------------------------------
extern "C" void kernel_launch(void* const* d_in, const int* in_sizes, int n_in,
                              void* d_out, int out_size)
{
    const float* feat   = (const float*)d_in[0];
    const float* proj_w = (const float*)d_in[2];
    const float* proj_b = (const float*)d_in[3];
    const float* pe     = (const float*)d_in[4];
    const float* qkv_w  = (const float*)d_in[5];
    const float* qkv_b  = (const float*)d_in[6];
    const float* out_w  = (const float*)d_in[7];
    const float* out_b  = (const float*)d_in[8];
    const float* ff1_w  = (const float*)d_in[9];
    const float* ff1_b  = (const float*)d_in[10];
    const float* ff2_w  = (const float*)d_in[11];
    const float* ff2_b  = (const float*)d_in[12];
    const float* ln1_g  = (const float*)d_in[13];
    const float* ln1_b  = (const float*)d_in[14];
    const float* ln2_g  = (const float*)d_in[15];
    const float* ln2_b  = (const float*)d_in[16];

    float *x, *y;
    __nv_bfloat16 *qh, *ql, *xh, *xl, *ah, *al, *fh, *fl;
    __nv_bfloat16 *wqh, *wql, *woh, *wol, *w1h, *w1l, *w2h, *w2l;
    cudaGetSymbolAddress((void**)&x,   g_x);
    cudaGetSymbolAddress((void**)&y,   g_y);
    cudaGetSymbolAddress((void**)&qh,  g_qh);  cudaGetSymbolAddress((void**)&ql, g_ql);
    cudaGetSymbolAddress((void**)&xh,  g_xh);  cudaGetSymbolAddress((void**)&xl, g_xl);
    cudaGetSymbolAddress((void**)&ah,  g_ah);  cudaGetSymbolAddress((void**)&al, g_al);
    cudaGetSymbolAddress((void**)&fh,  g_fh);  cudaGetSymbolAddress((void**)&fl, g_fl);
    cudaGetSymbolAddress((void**)&wqh, g_wqh); cudaGetSymbolAddress((void**)&wql, g_wql);
    cudaGetSymbolAddress((void**)&woh, g_woh); cudaGetSymbolAddress((void**)&wol, g_wol);
    cudaGetSymbolAddress((void**)&w1h, g_w1h); cudaGetSymbolAddress((void**)&w1l, g_w1l);
    cudaGetSymbolAddress((void**)&w2h, g_w2h); cudaGetSymbolAddress((void**)&w2l, g_w2l);

    cudaFuncSetAttribute(attn_tc,    cudaFuncAttributeMaxDynamicSharedMemorySize, ATT_SMEM);
    cudaFuncSetAttribute(tc_gemm<0>, cudaFuncAttributeMaxDynamicSharedMemorySize, GS_TOTAL);
    cudaFuncSetAttribute(tc_gemm<1>, cudaFuncAttributeMaxDynamicSharedMemorySize, GS_TOTAL);
    cudaFuncSetAttribute(tc_gemm<2>, cudaFuncAttributeMaxDynamicSharedMemorySize, GS_TOTAL);
    cudaFuncSetAttribute(tc_gemm<3>, cudaFuncAttributeMaxDynamicSharedMemorySize, GS_TOTAL);

    {
        int n4;
        n4 = NLAYER*3*Dm*Dm/4; split4_kernel<<<(n4+255)/256,256>>>(qkv_w, wqh, wql, n4);
        n4 = NLAYER*Dm*Dm/4;   split4_kernel<<<(n4+255)/256,256>>>(out_w, woh, wol, n4);
        n4 = NLAYER*FFd*Dm/4;  split4_kernel<<<(n4+255)/256,256>>>(ff1_w, w1h, w1l, n4);
        n4 = NLAYER*Dm*FFd/4;  split4_kernel<<<(n4+255)/256,256>>>(ff2_w, w2h, w2l, n4);
    }

    inproj_kernel<<<ROWS, 128>>>(feat, proj_w, proj_b, pe, x, xh, xl);

    for (int l = 0; l < NLAYER; l++) {
        // QKV -> bf16 hi/lo directly
        tc_gemm<3><<<dim3(3*Dm/256, ROWS/128), 256, GS_TOTAL>>>(
            xh, xl, wqh + (size_t)l*3*Dm*Dm, wql + (size_t)l*3*Dm*Dm,
            qkv_b + (size_t)l*3*Dm, nullptr, nullptr, qh, ql,
            ROWS, 3*Dm, Dm);
        // tensor-core banded attention -> (ah, al)
        attn_tc<<<dim3(Tseq/64, Hh, Bsz), 256, ATT_SMEM>>>(qh, ql, ah, al);
        // out proj + residual(x) -> y
        tc_gemm<1><<<dim3(Dm/256, ROWS/128), 256, GS_TOTAL>>>(
            ah, al, woh + (size_t)l*Dm*Dm, wol + (size_t)l*Dm*Dm,
            out_b + (size_t)l*Dm, x, y, nullptr, nullptr,
            ROWS, Dm, Dm);
        ln_kernel<<<ROWS, 256>>>(y, ln1_g + (size_t)l*Dm, ln1_b + (size_t)l*Dm, x, xh, xl);
        tc_gemm<2><<<dim3(FFd/256, ROWS/128), 256, GS_TOTAL>>>(
            xh, xl, w1h + (size_t)l*FFd*Dm, w1l + (size_t)l*FFd*Dm,
            ff1_b + (size_t)l*FFd, nullptr, nullptr, fh, fl,
            ROWS, FFd, Dm);
        tc_gemm<1><<<dim3(Dm/256, ROWS/128), 256, GS_TOTAL>>>(
            fh, fl, w2h + (size_t)l*Dm*FFd, w2l + (size_t)l*Dm*FFd,
            ff2_b + (size_t)l*Dm, x, y, nullptr, nullptr,
            ROWS, Dm, FFd);
        if (l == NLAYER - 1)
            ln_kernel<<<ROWS, 256>>>(y, ln2_g + (size_t)l*Dm, ln2_b + (size_t)l*Dm,
                                     (float*)d_out, nullptr, nullptr);
        else
            ln_kernel<<<ROWS, 256>>>(y, ln2_g + (size_t)l*Dm, ln2_b + (size_t)l*Dm, x, xh, xl);
    }
}

// round 7
// speedup vs baseline: 4.5734x; 1.9096x over previous
#include <cuda_runtime.h>
#include <cuda_fp16.h>
#include <cstdint>
#include <cstddef>

#define Bsz 4
#define Tseq 2048
#define Dm 512
#define Hh 8
#define FFd 2048
#define NLAYER 4
#define ROWS (Bsz*Tseq)   /* 8192 */

// ---------------- scratch (device globals; no allocations allowed) ----------
__device__ __align__(128) float g_x [ROWS*Dm];
__device__ __align__(128) float g_y [ROWS*Dm];
__device__ __align__(128) __half g_q [ROWS*3*Dm];
__device__ __align__(128) __half g_xa[ROWS*Dm];
__device__ __align__(128) __half g_a [ROWS*Dm];
__device__ __align__(128) __half g_f [ROWS*FFd];
__device__ __align__(128) __half g_wq[NLAYER*3*Dm*Dm];
__device__ __align__(128) __half g_wo[NLAYER*Dm*Dm];
__device__ __align__(128) __half g_w1[NLAYER*FFd*Dm];
__device__ __align__(128) __half g_w2[NLAYER*Dm*FFd];

// ---------------- helpers ----------------------------------------------------
__device__ __forceinline__ void cp16(uint32_t s, const void* g) {
    asm volatile("cp.async.cg.shared.global [%0], [%1], 16;" :: "r"(s), "l"(g));
}
__device__ __forceinline__ void cp_commit() {
    asm volatile("cp.async.commit_group;" ::: "memory");
}
template<int N> __device__ __forceinline__ void cp_wait() {
    asm volatile("cp.async.wait_group %0;" :: "n"(N) : "memory");
}
__device__ __forceinline__ void ldsm4(uint32_t* r, uint32_t addr) {
    asm volatile("ldmatrix.sync.aligned.m8n8.x4.shared.b16 {%0,%1,%2,%3}, [%4];"
                 : "=r"(r[0]), "=r"(r[1]), "=r"(r[2]), "=r"(r[3]) : "r"(addr));
}
__device__ __forceinline__ void mma16816(float* c, const uint32_t* a, const uint32_t* b) {
    asm volatile(
        "mma.sync.aligned.m16n8k16.row.col.f32.f16.f16.f32 "
        "{%0,%1,%2,%3}, {%4,%5,%6,%7}, {%8,%9}, {%0,%1,%2,%3};"
        : "+f"(c[0]), "+f"(c[1]), "+f"(c[2]), "+f"(c[3])
        : "r"(a[0]), "r"(a[1]), "r"(a[2]), "r"(a[3]), "r"(b[0]), "r"(b[1]));
}

// ---------------- weight fp32 -> fp16 convert --------------------------------
__global__ __launch_bounds__(256)
void cvt4_kernel(const float* __restrict__ w, __half* __restrict__ h, int n4) {
    int i = blockIdx.x * 256 + threadIdx.x;
    if (i < n4) {
        float4 v = ((const float4*)w)[i];
        __half2 a = __floats2half2_rn(v.x, v.y);
        __half2 b = __floats2half2_rn(v.z, v.w);
        ((__half2*)h)[i*2]     = a;
        ((__half2*)h)[i*2 + 1] = b;
    }
}

// ---------------- HMMA GEMM: C[M,N] = A[M,K] @ W[N,K]^T ----------------------
// fp16 x fp16 -> fp32 acc, single term.
// BM=128, BN=256, BK=32, 256 threads (8 warps, warp tile 64x64), 3-stage cp.async.
// MODE 0: Cf = acc + bias
// MODE 1: Cf = acc + bias + res
// MODE 2: Ch = fp16(relu(acc + bias))
// MODE 3: Ch = fp16(acc + bias)
#define AROW 80
#define A_TILE (128*AROW)            /* 10240 */
#define B_TILE (256*AROW)            /* 20480 */
#define STAGE_B (A_TILE + B_TILE)    /* 30720 */
#define NSTAGE 3
#define GS_TOTAL (NSTAGE*STAGE_B)    /* 92160 */

__device__ __forceinline__ void gload(uint32_t st,
    const __half* __restrict__ A, const __half* __restrict__ B,
    int bm, int bn, int K, int k0, int tid)
{
    #pragma unroll
    for (int i = 0; i < 2; i++) {                 // A: 128 rows x 64B
        int idx = tid + i * 256;                  // 0..511
        int row = idx >> 2, c = idx & 3;
        uint32_t so = (uint32_t)(row * AROW + c * 16);
        cp16(st + so, A + (size_t)(bm + row) * K + k0 + c * 8);
    }
    #pragma unroll
    for (int i = 0; i < 4; i++) {                 // B: 256 rows x 64B
        int idx = tid + i * 256;                  // 0..1023
        int row = idx >> 2, c = idx & 3;
        uint32_t so = (uint32_t)(row * AROW + c * 16);
        cp16(st + A_TILE + so, B + (size_t)(bn + row) * K + k0 + c * 8);
    }
    cp_commit();
}

template<int MODE>
__global__ __launch_bounds__(256, 1)
void tc_gemm(const __half* __restrict__ A, const __half* __restrict__ B,
             const float* __restrict__ bias, const float* __restrict__ res,
             float* __restrict__ Cf, __half* __restrict__ Ch,
             int M, int N, int K)
{
    extern __shared__ __align__(128) char smem[];
    uint32_t sb = (uint32_t)__cvta_generic_to_shared(smem);
    int tid = threadIdx.x;
    int wid = tid >> 5, lane = tid & 31;
    int bn = blockIdx.x * 256, bm = blockIdx.y * 128;
    int wm = (wid & 1) * 64;
    int wn = (wid >> 1) * 64;

    float acc[4][8][4];
    #pragma unroll
    for (int i = 0; i < 4; i++)
        #pragma unroll
        for (int j = 0; j < 8; j++)
            #pragma unroll
            for (int r = 0; r < 4; r++) acc[i][j][r] = 0.f;

    const int C = K >> 5;
    gload(sb,           A, B, bm, bn, K, 0,  tid);
    gload(sb + STAGE_B, A, B, bm, bn, K, 32, tid);

    uint32_t a_row = (uint32_t)(lane & 15);
    uint32_t a_koff = (uint32_t)((lane >> 4) * 16);
    uint32_t b_row = (uint32_t)((lane & 7) + ((lane >> 4) << 3));
    uint32_t b_koff = (uint32_t)(((lane >> 3) & 1) * 16);

    for (int c = 0; c < C; c++) {
        if (c + 1 < C) cp_wait<1>(); else cp_wait<0>();
        __syncthreads();
        if (c + 2 < C)
            gload(sb + ((c + 2) % NSTAGE) * STAGE_B, A, B, bm, bn, K, (c + 2) * 32, tid);

        uint32_t sa = sb + (c % NSTAGE) * STAGE_B;
        #pragma unroll
        for (int kk = 0; kk < 2; kk++) {
            uint32_t kb = (uint32_t)(kk * 32);
            uint32_t af[4][4];
            #pragma unroll
            for (int mt = 0; mt < 4; mt++) {
                uint32_t ad = sa + (wm + mt*16 + a_row) * AROW + kb + a_koff;
                ldsm4(af[mt], ad);
            }
            #pragma unroll
            for (int ng = 0; ng < 4; ng++) {
                uint32_t bf[4];
                uint32_t bd = sa + A_TILE + (wn + ng*16 + b_row) * AROW + kb + b_koff;
                ldsm4(bf, bd);
                #pragma unroll
                for (int mt = 0; mt < 4; mt++)
                    #pragma unroll
                    for (int half = 0; half < 2; half++)
                        mma16816(acc[mt][ng*2 + half], af[mt], &bf[half*2]);
            }
        }
    }

    #pragma unroll
    for (int mt = 0; mt < 4; mt++) {
        int m0 = bm + wm + mt*16 + (lane >> 2);
        #pragma unroll
        for (int nt = 0; nt < 8; nt++) {
            int n = bn + wn + nt*8 + (lane & 3)*2;
            float bx = bias[n], by = bias[n+1];
            #pragma unroll
            for (int h = 0; h < 2; h++) {
                int m = m0 + h*8;
                float v0 = acc[mt][nt][h*2]   + bx;
                float v1 = acc[mt][nt][h*2+1] + by;
                size_t idx = (size_t)m * N + n;
                if (MODE == 1) {
                    float2 rv = *(const float2*)&res[idx];
                    v0 += rv.x; v1 += rv.y;
                }
                if (MODE == 2 || MODE == 3) {
                    if (MODE == 2) { v0 = fmaxf(v0, 0.f); v1 = fmaxf(v1, 0.f); }
                    *(__half2*)(Ch + idx) = __floats2half2_rn(v0, v1);
                } else {
                    *(float2*)&Cf[idx] = make_float2(v0, v1);
                }
            }
        }
    }
}

// ---------------- tensor-core banded attention (fp16) ------------------------
#define OFF_QH 0
#define OFF_KH 9216    /* also VT in phase C */
#define OFF_S  18432   /* fp32 [64][328] */
#define OFF_PH 102400  /* fp16 [64][344] */
#define ATT_SMEM 146432

__global__ __launch_bounds__(256, 1)
void attn_tc(const __half* __restrict__ q, __half* __restrict__ outp)
{
    extern __shared__ __align__(128) char smraw[];
    uint32_t sb = (uint32_t)__cvta_generic_to_shared(smraw);
    float* S = (float*)(smraw + OFF_S);

    int tid = threadIdx.x;
    int wid = tid >> 5, lane = tid & 31;
    int b = blockIdx.z, h = blockIdx.y;
    int qstart = blockIdx.x << 6;
    size_t rowbase = (size_t)b * Tseq;
    int wm = (wid & 1) * 32;
    int wn = (wid >> 1) * 16;

    uint32_t a_row = (uint32_t)(lane & 15);
    uint32_t a_koff = (uint32_t)((lane >> 4) * 16);
    uint32_t b_row = (uint32_t)((lane & 7) + ((lane >> 4) << 3));
    uint32_t b_koff = (uint32_t)(((lane >> 3) & 1) * 16);

    // ---- fill Q tile (64 rows x 64 fp16, pitch 144 B) ----
    #pragma unroll
    for (int r = 0; r < 2; r++) {
        int idx = tid + r*256;
        int qi = idx >> 3, seg = idx & 7;
        size_t go = (rowbase + qstart + qi)*1536 + h*64 + seg*8;
        *(uint4*)(smraw + OFF_QH + qi*144 + seg*16) = *(const uint4*)(q + go);
    }
    __syncthreads();

    // ---- hoist Q fragments ----
    uint32_t af[2][4][4];
    #pragma unroll
    for (int mt = 0; mt < 2; mt++)
        #pragma unroll
        for (int ks = 0; ks < 4; ks++) {
            uint32_t ad = sb + OFF_QH + (wm + mt*16 + a_row)*144 + ks*32 + a_koff;
            ldsm4(af[mt][ks], ad);
        }

    const float scale = 0.125f;

    // ---- phase A: S = Q K^T ----
    for (int kb = 0; kb < 5; kb++) {
        __syncthreads();
        #pragma unroll
        for (int r = 0; r < 2; r++) {
            int idx = tid + r*256;
            int kj = idx >> 3, seg = idx & 7;
            int ka = qstart - 128 + kb*64 + kj;
            uint4 v = make_uint4(0,0,0,0);
            if (ka >= 0 && ka < Tseq)
                v = *(const uint4*)(q + (rowbase + ka)*1536 + 512 + h*64 + seg*8);
            *(uint4*)(smraw + OFF_KH + kj*144 + seg*16) = v;
        }
        __syncthreads();

        float acc[2][2][4];
        #pragma unroll
        for (int i = 0; i < 2; i++)
            #pragma unroll
            for (int j = 0; j < 2; j++)
                #pragma unroll
                for (int r = 0; r < 4; r++) acc[i][j][r] = 0.f;

        #pragma unroll
        for (int ks = 0; ks < 4; ks++) {
            uint32_t bf[4];
            uint32_t bd = sb + OFF_KH + (wn + b_row)*144 + ks*32 + b_koff;
            ldsm4(bf, bd);
            #pragma unroll
            for (int mt = 0; mt < 2; mt++)
                #pragma unroll
                for (int half = 0; half < 2; half++)
                    mma16816(acc[mt][half], af[mt][ks], &bf[half*2]);
        }

        #pragma unroll
        for (int mt = 0; mt < 2; mt++)
            #pragma unroll
            for (int half = 0; half < 2; half++)
                #pragma unroll
                for (int r = 0; r < 4; r++) {
                    int qi   = wm + mt*16 + (lane >> 2) + (r >> 1)*8;
                    int kidx = kb*64 + wn + half*8 + (lane & 3)*2 + (r & 1);
                    int ka   = qstart - 128 + kidx;
                    int delta = kidx - qi;
                    bool ok = (delta >= 0) && (delta <= 256) && (ka >= 0) && (ka < Tseq);
                    S[qi*328 + kidx] = ok ? acc[mt][half][r] * scale : -1e30f;
                }
    }
    __syncthreads();

    // ---- softmax + P -> fp16 (1/sum folded) ----
    {
        __half* PH = (__half*)(smraw + OFF_PH);
        for (int qq = wid*8; qq < wid*8 + 8; qq++) {
            float v[10]; float m = -1e30f;
            #pragma unroll
            for (int i = 0; i < 10; i++) { v[i] = S[qq*328 + lane + i*32]; m = fmaxf(m, v[i]); }
            #pragma unroll
            for (int o = 16; o > 0; o >>= 1) m = fmaxf(m, __shfl_xor_sync(0xffffffffu, m, o));
            float ssum = 0.f;
            #pragma unroll
            for (int i = 0; i < 10; i++) { v[i] = __expf(v[i] - m); ssum += v[i]; }
            #pragma unroll
            for (int o = 16; o > 0; o >>= 1) ssum += __shfl_xor_sync(0xffffffffu, ssum, o);
            float rs = 1.0f / ssum;
            #pragma unroll
            for (int i = 0; i < 10; i++)
                PH[qq*344 + lane + i*32] = __float2half(v[i] * rs);
        }
    }

    // ---- phase C: O = P V (V transposed into SMEM) ----
    float oacc[2][2][4];
    #pragma unroll
    for (int i = 0; i < 2; i++)
        #pragma unroll
        for (int j = 0; j < 2; j++)
            #pragma unroll
            for (int r = 0; r < 4; r++) oacc[i][j][r] = 0.f;

    for (int kb = 0; kb < 5; kb++) {
        __syncthreads();
        #pragma unroll
        for (int r = 0; r < 2; r++) {
            int idx = tid + r*256;
            int kj = idx >> 3, seg = idx & 7;
            int d0 = seg * 8;
            int ka = qstart - 128 + kb*64 + kj;
            union U8 { uint4 u; __half e[8]; } v;
            v.u = make_uint4(0,0,0,0);
            if (ka >= 0 && ka < Tseq)
                v.u = *(const uint4*)(q + (rowbase + ka)*1536 + 1024 + h*64 + d0);
            __half* VT = (__half*)(smraw + OFF_KH);
            #pragma unroll
            for (int j = 0; j < 8; j++)
                VT[(d0 + j)*72 + kj] = v.e[j];
        }
        __syncthreads();

        #pragma unroll
        for (int ks = 0; ks < 4; ks++) {
            uint32_t aP[2][4];
            #pragma unroll
            for (int mt = 0; mt < 2; mt++) {
                uint32_t pd = sb + OFF_PH + (wm + mt*16 + a_row)*688 + (kb*64 + ks*16)*2 + a_koff;
                ldsm4(aP[mt], pd);
            }
            uint32_t bf[4];
            uint32_t bd = sb + OFF_KH + (wn + b_row)*144 + ks*32 + b_koff;
            ldsm4(bf, bd);
            #pragma unroll
            for (int mt = 0; mt < 2; mt++)
                #pragma unroll
                for (int half = 0; half < 2; half++)
                    mma16816(oacc[mt][half], aP[mt], &bf[half*2]);
        }
    }

    #pragma unroll
    for (int mt = 0; mt < 2; mt++)
        #pragma unroll
        for (int half = 0; half < 2; half++)
            #pragma unroll
            for (int hr = 0; hr < 2; hr++) {
                int qi = wm + mt*16 + (lane >> 2) + hr*8;
                int d  = wn + half*8 + (lane & 3)*2;
                size_t idx = (rowbase + qstart + qi)*512 + h*64 + d;
                *(__half2*)(outp + idx) =
                    __floats2half2_rn(oacc[mt][half][hr*2], oacc[mt][half][hr*2+1]);
            }
}

// ---------------- LayerNorm (+ optional fp16 output) -------------------------
__global__ __launch_bounds__(256)
void ln_kernel(const float* __restrict__ in, const float* __restrict__ gam,
               const float* __restrict__ bet, float* __restrict__ out,
               __half* __restrict__ oh)
{
    int row = blockIdx.x, tid = threadIdx.x;
    const float* p = in + (size_t)row * 512;
    float x0 = p[tid], x1 = p[tid + 256];
    float s = x0 + x1, q = x0*x0 + x1*x1;
    #pragma unroll
    for (int o = 16; o > 0; o >>= 1) {
        s += __shfl_xor_sync(0xffffffffu, s, o);
        q += __shfl_xor_sync(0xffffffffu, q, o);
    }
    __shared__ float ss[8], sq[8];
    int w = tid >> 5, l = tid & 31;
    if (l == 0) { ss[w] = s; sq[w] = q; }
    __syncthreads();
    float ts = 0.f, tq = 0.f;
    #pragma unroll
    for (int i = 0; i < 8; i++) { ts += ss[i]; tq += sq[i]; }
    float mean = ts * (1.0f/512.0f);
    float var  = tq * (1.0f/512.0f) - mean*mean;
    float inv  = rsqrtf(var + 1e-5f);
    float v0 = (x0 - mean) * inv * gam[tid]       + bet[tid];
    float v1 = (x1 - mean) * inv * gam[tid + 256] + bet[tid + 256];
    float* o = out + (size_t)row * 512;
    o[tid]       = v0;
    o[tid + 256] = v1;
    if (oh) {
        oh[(size_t)row*512 + tid]       = __float2half(v0);
        oh[(size_t)row*512 + tid + 256] = __float2half(v1);
    }
}

// ---------------- input projection ------------------------------------------
__global__ __launch_bounds__(128)
void inproj_kernel(const float* __restrict__ feat, const float* __restrict__ w,
                   const float* __restrict__ bias, const float* __restrict__ pe,
                   float* __restrict__ out, __half* __restrict__ oh)
{
    int row = blockIdx.x;
    int t = row & (Tseq - 1);
    __shared__ float f[32];
    if (threadIdx.x < 32) f[threadIdx.x] = feat[(size_t)row*32 + threadIdx.x];
    __syncthreads();
    int d0 = threadIdx.x * 4;
    float a[4];
    #pragma unroll
    for (int j = 0; j < 4; j++) a[j] = bias[d0 + j];
    #pragma unroll
    for (int j = 0; j < 4; j++) {
        const float4* wp = (const float4*)(w + (size_t)(d0 + j) * 32);
        #pragma unroll
        for (int k4 = 0; k4 < 8; k4++) {
            float4 wv = wp[k4];
            a[j] += wv.x*f[k4*4] + wv.y*f[k4*4+1] + wv.z*f[k4*4+2] + wv.w*f[k4*4+3];
        }
    }
    float4 pev = *(const float4*)(pe + (size_t)t*512 + d0);
    float4 r = make_float4(a[0]+pev.x, a[1]+pev.y, a[2]+pev.z, a[3]+pev.w);
    *(float4*)(out + (size_t)row*512 + d0) = r;
    __half2 h01 = __floats2half2_rn(r.x, r.y);
    __half2 h23 = __floats2half2_rn(r.z, r.w);
    *(__half2*)(oh + (size_t)row*512 + d0)     = h01;
    *(__half2*)(oh + (size_t)row*512 + d0 + 2) = h23;
}

// ---------------- launch ----------------------------------------------------
extern "C" void kernel_launch(void* const* d_in, const int* in_sizes, int n_in,
                              void* d_out, int out_size)
{
    const float* feat   = (const float*)d_in[0];
    const float* proj_w = (const float*)d_in[2];
    const float* proj_b = (const float*)d_in[3];
    const float* pe     = (const float*)d_in[4];
    const float* qkv_w  = (const float*)d_in[5];
    const float* qkv_b  = (const float*)d_in[6];
    const float* out_w  = (const float*)d_in[7];
    const float* out_b  = (const float*)d_in[8];
    const float* ff1_w  = (const float*)d_in[9];
    const float* ff1_b  = (const float*)d_in[10];
    const float* ff2_w  = (const float*)d_in[11];
    const float* ff2_b  = (const float*)d_in[12];
    const float* ln1_g  = (const float*)d_in[13];
    const float* ln1_b  = (const float*)d_in[14];
    const float* ln2_g  = (const float*)d_in[15];
    const float* ln2_b  = (const float*)d_in[16];

    float *x, *y;
    __half *q, *xa, *a, *f, *wq, *wo, *w1, *w2;
    cudaGetSymbolAddress((void**)&x,  g_x);
    cudaGetSymbolAddress((void**)&y,  g_y);
    cudaGetSymbolAddress((void**)&q,  g_q);
    cudaGetSymbolAddress((void**)&xa, g_xa);
    cudaGetSymbolAddress((void**)&a,  g_a);
    cudaGetSymbolAddress((void**)&f,  g_f);
    cudaGetSymbolAddress((void**)&wq, g_wq);
    cudaGetSymbolAddress((void**)&wo, g_wo);
    cudaGetSymbolAddress((void**)&w1, g_w1);
    cudaGetSymbolAddress((void**)&w2, g_w2);

    cudaFuncSetAttribute(attn_tc,    cudaFuncAttributeMaxDynamicSharedMemorySize, ATT_SMEM);
    cudaFuncSetAttribute(tc_gemm<0>, cudaFuncAttributeMaxDynamicSharedMemorySize, GS_TOTAL);
    cudaFuncSetAttribute(tc_gemm<1>, cudaFuncAttributeMaxDynamicSharedMemorySize, GS_TOTAL);
    cudaFuncSetAttribute(tc_gemm<2>, cudaFuncAttributeMaxDynamicSharedMemorySize, GS_TOTAL);
    cudaFuncSetAttribute(tc_gemm<3>, cudaFuncAttributeMaxDynamicSharedMemorySize, GS_TOTAL);

    {
        int n4;
        n4 = NLAYER*3*Dm*Dm/4; cvt4_kernel<<<(n4+255)/256,256>>>(qkv_w, wq, n4);
        n4 = NLAYER*Dm*Dm/4;   cvt4_kernel<<<(n4+255)/256,256>>>(out_w, wo, n4);
        n4 = NLAYER*FFd*Dm/4;  cvt4_kernel<<<(n4+255)/256,256>>>(ff1_w, w1, n4);
        n4 = NLAYER*Dm*FFd/4;  cvt4_kernel<<<(n4+255)/256,256>>>(ff2_w, w2, n4);
    }

    inproj_kernel<<<ROWS, 128>>>(feat, proj_w, proj_b, pe, x, xa);

    for (int l = 0; l < NLAYER; l++) {
        // QKV -> fp16 directly
        tc_gemm<3><<<dim3(3*Dm/256, ROWS/128), 256, GS_TOTAL>>>(
            xa, wq + (size_t)l*3*Dm*Dm, qkv_b + (size_t)l*3*Dm, nullptr,
            nullptr, q, ROWS, 3*Dm, Dm);
        // tensor-core banded attention -> a (fp16)
        attn_tc<<<dim3(Tseq/64, Hh, Bsz), 256, ATT_SMEM>>>(q, a);
        // out proj + residual(x) -> y
        tc_gemm<1><<<dim3(Dm/256, ROWS/128), 256, GS_TOTAL>>>(
            a, wo + (size_t)l*Dm*Dm, out_b + (size_t)l*Dm, x,
            y, nullptr, ROWS, Dm, Dm);
        ln_kernel<<<ROWS, 256>>>(y, ln1_g + (size_t)l*Dm, ln1_b + (size_t)l*Dm, x, xa);
        // FF1 + ReLU -> f (fp16)
        tc_gemm<2><<<dim3(FFd/256, ROWS/128), 256, GS_TOTAL>>>(
            xa, w1 + (size_t)l*FFd*Dm, ff1_b + (size_t)l*FFd, nullptr,
            nullptr, f, ROWS, FFd, Dm);
        // FF2 + residual(x) -> y
        tc_gemm<1><<<dim3(Dm/256, ROWS/128), 256, GS_TOTAL>>>(
            f, w2 + (size_t)l*Dm*FFd, ff2_b + (size_t)l*Dm, x,
            y, nullptr, ROWS, Dm, FFd);
        if (l == NLAYER - 1)
            ln_kernel<<<ROWS, 256>>>(y, ln2_g + (size_t)l*Dm, ln2_b + (size_t)l*Dm,
                                     (float*)d_out, nullptr);
        else
            ln_kernel<<<ROWS, 256>>>(y, ln2_g + (size_t)l*Dm, ln2_b + (size_t)l*Dm, x, xa);
    }
}